// round 7
// baseline (speedup 1.0000x reference)
#include <cuda_runtime.h>
#include <cuda_bf16.h>
#include <cstdint>

#define Nn   100000
#define Fdim 512
#define Hdim 64
#define Cdim 40
#define Ed   1600000
#define HC   896      // F + 6*H  (hcat width)
#define NB_SCAN 391   // ceil(Nn/256)

// ---------------- scratch (device globals; no allocation allowed) ----------
__device__ __nv_bfloat16 g_hcat_hi[(size_t)Nn * HC];  // 179 MB
__device__ __nv_bfloat16 g_hcat_lo[(size_t)Nn * HC];  // 179 MB
__device__ float g_lin[(size_t)Nn * Hdim];            // GEMM output (64 cols)
__device__ float g_dinv[Nn];
__device__ int   g_deg[Nn];
__device__ int   g_off[Nn];                           // CSR offsets (exclusive scan of deg)
__device__ int   g_cursor[Nn];
__device__ int   g_bsum[NB_SCAN];
__device__ int   g_esrc[Ed];                          // CSR: source node per edge slot
__device__ __nv_bfloat16 g_Wt_hi[64 * HC];            // weights transposed [n][k]
__device__ __nv_bfloat16 g_Wt_lo[64 * HC];

// ---------------- tiny PTX helpers ----------------------------------------
__device__ __forceinline__ uint32_t smem_u32(const void* p) {
    uint32_t a;
    asm("{ .reg .u64 t; cvta.to.shared.u64 t, %1; cvt.u32.u64 %0, t; }" : "=r"(a) : "l"(p));
    return a;
}
__device__ __forceinline__ uint32_t swz64(uint32_t off) { return off ^ ((off >> 3) & 0x30); }

__device__ __forceinline__ void cp16(uint32_t dst, const void* src, int sz) {
    asm volatile("cp.async.cg.shared.global [%0], [%1], 16, %2;"
                 :: "r"(dst), "l"(src), "r"(sz) : "memory");
}
__device__ __forceinline__ void ldm_x4(uint32_t* r, uint32_t addr) {
    asm volatile("ldmatrix.sync.aligned.m8n8.x4.shared.b16 {%0,%1,%2,%3}, [%4];"
                 : "=r"(r[0]), "=r"(r[1]), "=r"(r[2]), "=r"(r[3]) : "r"(addr));
}
__device__ __forceinline__ void mma16816(float* d, const uint32_t* a, const uint32_t* b) {
    asm volatile("mma.sync.aligned.m16n8k16.row.col.f32.bf16.bf16.f32 "
                 "{%0,%1,%2,%3},{%4,%5,%6,%7},{%8,%9},{%0,%1,%2,%3};"
                 : "+f"(d[0]), "+f"(d[1]), "+f"(d[2]), "+f"(d[3])
                 : "r"(a[0]), "r"(a[1]), "r"(a[2]), "r"(a[3]), "r"(b[0]), "r"(b[1]));
}

// ---------------- degree / norm -------------------------------------------
__global__ void k_zero_deg() {
    int i = blockIdx.x * 256 + threadIdx.x;
    if (i < Nn) g_deg[i] = 0;
}
__global__ void k_count(const int* __restrict__ col) {
    int e = blockIdx.x * 256 + threadIdx.x;
    if (e < Ed) atomicAdd(&g_deg[col[e]], 1);
}
__global__ void k_dinv() {
    int i = blockIdx.x * 256 + threadIdx.x;
    if (i < Nn) g_dinv[i] = rsqrtf((float)(g_deg[i] + 1));  // +1 self loop
}

// ---------------- CSR build: scan + counting sort -------------------------
__global__ void k_scan1() {
    __shared__ int sh[256];
    int b = blockIdx.x, t = threadIdx.x;
    int i = b * 256 + t;
    int v = (i < Nn) ? g_deg[i] : 0;
    sh[t] = v;
    __syncthreads();
    int acc = v;
#pragma unroll
    for (int d = 1; d < 256; d <<= 1) {
        int u = (t >= d) ? sh[t - d] : 0;
        __syncthreads();
        acc += u;
        sh[t] = acc;
        __syncthreads();
    }
    if (i < Nn) g_off[i] = acc - v;
    if (t == 255) g_bsum[b] = acc;
}
__global__ void k_scan2() {
    __shared__ int sh[512];
    int t = threadIdx.x;
    int v = (t < NB_SCAN) ? g_bsum[t] : 0;
    sh[t] = v;
    __syncthreads();
    int acc = v;
#pragma unroll
    for (int d = 1; d < 512; d <<= 1) {
        int u = (t >= d) ? sh[t - d] : 0;
        __syncthreads();
        acc += u;
        sh[t] = acc;
        __syncthreads();
    }
    if (t < NB_SCAN) g_bsum[t] = acc - v;
}
__global__ void k_scan3() {
    int i = blockIdx.x * 256 + threadIdx.x;
    if (i >= Nn) return;
    int o = g_off[i] + g_bsum[i >> 8];
    g_off[i] = o;
    g_cursor[i] = o;
}
__global__ void k_build(const int* __restrict__ rowi, const int* __restrict__ coli) {
    int e = blockIdx.x * 256 + threadIdx.x;
    if (e >= Ed) return;
    int pos = atomicAdd(&g_cursor[coli[e]], 1);
    g_esrc[pos] = rowi[e];
}

// ---------------- convert x -> hcat hi/lo [:, 0:512] ----------------------
__global__ void k_convx(const float* __restrict__ x) {
    int idx = blockIdx.x * 256 + threadIdx.x;     // Nn*128 float4s
    if (idx >= Nn * 128) return;
    int n = idx >> 7, q = idx & 127;
    float4 v = ((const float4*)x)[(size_t)n * 128 + q];
    size_t o = (size_t)n * HC + q * 4;
    __nv_bfloat16 h0 = __float2bfloat16(v.x), h1 = __float2bfloat16(v.y);
    __nv_bfloat16 h2 = __float2bfloat16(v.z), h3 = __float2bfloat16(v.w);
    __nv_bfloat16 l0 = __float2bfloat16(v.x - __bfloat162float(h0));
    __nv_bfloat16 l1 = __float2bfloat16(v.y - __bfloat162float(h1));
    __nv_bfloat16 l2 = __float2bfloat16(v.z - __bfloat162float(h2));
    __nv_bfloat16 l3 = __float2bfloat16(v.w - __bfloat162float(h3));
    *(__nv_bfloat162*)(g_hcat_hi + o)     = __nv_bfloat162(h0, h1);
    *(__nv_bfloat162*)(g_hcat_hi + o + 2) = __nv_bfloat162(h2, h3);
    *(__nv_bfloat162*)(g_hcat_lo + o)     = __nv_bfloat162(l0, l1);
    *(__nv_bfloat162*)(g_hcat_lo + o + 2) = __nv_bfloat162(l2, l3);
}

// ---------------- weight conversion: W[K][64] -> Wt hi/lo [64][896] -------
__global__ void k_convW(const float* __restrict__ W, int K) {
    int idx = blockIdx.x * 256 + threadIdx.x;
    if (idx >= K * 64) return;
    int k = idx >> 6, n = idx & 63;
    float w = W[idx];
    __nv_bfloat16 h = __float2bfloat16(w);
    __nv_bfloat16 l = __float2bfloat16(w - __bfloat162float(h));
    g_Wt_hi[n * HC + k] = h;
    g_Wt_lo[n * HC + k] = l;
}
__global__ void k_convWlin(const float* __restrict__ Wlin) {
    int idx = blockIdx.x * 256 + threadIdx.x;     // 896*64
    if (idx >= HC * 64) return;
    int k = idx >> 6, n = idx & 63;
    float w = (n < Cdim) ? Wlin[k * Cdim + n] : 0.f;
    __nv_bfloat16 h = __float2bfloat16(w);
    __nv_bfloat16 l = __float2bfloat16(w - __bfloat162float(h));
    g_Wt_hi[n * HC + k] = h;
    g_Wt_lo[n * HC + k] = l;
}

// ---------------- mma.sync GEMM: g_lin[N,64] = hcat[:, :K] @ W ------------
// CTA: 256 rows x 64 cols, 8 warps (each 32x64). bf16 hi/lo, 3 products.
// K-chunks of 32, double-buffered, SW64 swizzle (64B rows).
// Stage layout: A_hi [0,16K) A_lo [16K,32K) B_hi [32K,36K) B_lo [36K,40K)
#define STAGE_BYTES 40960
__global__ void __launch_bounds__(256, 2) k_gemm_mma(int K) {
    extern __shared__ char smem[];
    uint32_t sbase = smem_u32(smem);
    uint32_t data = (sbase + 1023) & ~1023u;

    int t = threadIdx.x, wid = t >> 5, lane = t & 31;
    int rowBase = blockIdx.x * 256;
    int m0 = wid * 32;

    float acc[2][8][4];
#pragma unroll
    for (int i = 0; i < 2; i++)
#pragma unroll
        for (int j = 0; j < 8; j++)
#pragma unroll
            for (int k = 0; k < 4; k++) acc[i][j][k] = 0.f;

    auto load_chunk = [&](int c, int s) {
        uint32_t sa = data + s * STAGE_BYTES;
        // A: 256 rows x 32 k = 1024 cp16 ops, 4 per thread (hi+lo)
#pragma unroll
        for (int i = 0; i < 4; i++) {
            int idx = t + i * 256;           // 0..1023
            int r = idx >> 2, g = idx & 3;
            int gr = rowBase + r;
            int sz = (gr < Nn) ? 16 : 0;
            int grc = (gr < Nn) ? gr : (Nn - 1);
            size_t go = (size_t)grc * HC + c * 32 + g * 8;
            uint32_t d = sa + swz64(r * 64 + g * 16);
            cp16(d, g_hcat_hi + go, sz);
            cp16(d + 16384, g_hcat_lo + go, sz);
        }
        // B: 64 rows x 32 k = 256 cp16 ops, 1 per thread (hi+lo)
        {
            int n = t >> 2, g = t & 3;
            size_t go = (size_t)n * HC + c * 32 + g * 8;
            uint32_t d = sa + 32768 + swz64(n * 64 + g * 16);
            cp16(d, g_Wt_hi + go, 16);
            cp16(d + 4096, g_Wt_lo + go, 16);
        }
        asm volatile("cp.async.commit_group;" ::: "memory");
    };

    int nC = K / 32;          // K is a multiple of 64, so also of 32
    load_chunk(0, 0);
    load_chunk(1, 1);

    for (int c = 0; c < nC; c++) {
        int s = c & 1;
        if (c + 1 < nC) asm volatile("cp.async.wait_group 1;" ::: "memory");
        else            asm volatile("cp.async.wait_group 0;" ::: "memory");
        __syncthreads();

        uint32_t sa = data + s * STAGE_BYTES;
#pragma unroll
        for (int ks = 0; ks < 2; ks++) {
            uint32_t ahi[2][4], alo[2][4];
#pragma unroll
            for (int mt = 0; mt < 2; mt++) {
                int row = m0 + mt * 16 + (lane & 15);
                uint32_t off = swz64(row * 64 + ks * 32 + (lane >> 4) * 16);
                ldm_x4(ahi[mt], sa + off);
                ldm_x4(alo[mt], sa + 16384 + off);
            }
            uint32_t bhi[8][2], blo[8][2];
#pragma unroll
            for (int j2 = 0; j2 < 4; j2++) {
                int nr = j2 * 16 + ((lane >> 4) * 8) + (lane & 7);
                int kh = (lane >> 3) & 1;
                uint32_t off = swz64(nr * 64 + ks * 32 + kh * 16);
                uint32_t tmp[4];
                ldm_x4(tmp, sa + 32768 + off);
                bhi[2 * j2][0] = tmp[0]; bhi[2 * j2][1] = tmp[1];
                bhi[2 * j2 + 1][0] = tmp[2]; bhi[2 * j2 + 1][1] = tmp[3];
                ldm_x4(tmp, sa + 36864 + off);
                blo[2 * j2][0] = tmp[0]; blo[2 * j2][1] = tmp[1];
                blo[2 * j2 + 1][0] = tmp[2]; blo[2 * j2 + 1][1] = tmp[3];
            }
#pragma unroll
            for (int mt = 0; mt < 2; mt++)
#pragma unroll
                for (int j = 0; j < 8; j++) {
                    mma16816(acc[mt][j], ahi[mt], bhi[j]);
                    mma16816(acc[mt][j], ahi[mt], blo[j]);
                    mma16816(acc[mt][j], alo[mt], bhi[j]);
                }
        }
        __syncthreads();
        if (c + 2 < nC) load_chunk(c + 2, s);
    }

    int rBase = rowBase + m0 + (lane >> 2);
    int cBase = (lane & 3) * 2;
#pragma unroll
    for (int mt = 0; mt < 2; mt++) {
        int r0 = rBase + mt * 16;
#pragma unroll
        for (int j = 0; j < 8; j++) {
            int col = j * 8 + cBase;
            if (r0 < Nn)
                *(float2*)(g_lin + (size_t)r0 * 64 + col) = make_float2(acc[mt][j][0], acc[mt][j][1]);
            if (r0 + 8 < Nn)
                *(float2*)(g_lin + (size_t)(r0 + 8) * 64 + col) = make_float2(acc[mt][j][2], acc[mt][j][3]);
        }
    }
}

// ---------------- fused CSR aggregate + self-loop + bias + relu + hi/lo ----
__global__ void k_agg_fused(const float* __restrict__ bias, int off) {
    int gid = blockIdx.x * 256 + threadIdx.x;
    int c = gid >> 3;
    if (c >= Nn) return;
    int q = gid & 7;

    int e0 = g_off[c];
    int d  = g_deg[c];
    float4 a0 = make_float4(0.f, 0.f, 0.f, 0.f);
    float4 a1 = make_float4(0.f, 0.f, 0.f, 0.f);
    for (int i = 0; i < d; i++) {
        int r = __ldg(&g_esrc[e0 + i]);
        float w = __ldg(&g_dinv[r]);
        const float4* src = ((const float4*)(g_lin + (size_t)r * 64)) + q * 2;
        float4 v0 = __ldg(src), v1 = __ldg(src + 1);
        a0.x += w * v0.x; a0.y += w * v0.y; a0.z += w * v0.z; a0.w += w * v0.w;
        a1.x += w * v1.x; a1.y += w * v1.y; a1.z += w * v1.z; a1.w += w * v1.w;
    }
    float dc = g_dinv[c];
    float dc2 = dc * dc;
    const float4* sl = ((const float4*)(g_lin + (size_t)c * 64)) + q * 2;
    float4 s0 = __ldg(sl), s1 = __ldg(sl + 1);
    float4 b0 = ((const float4*)bias)[q * 2];
    float4 b1 = ((const float4*)bias)[q * 2 + 1];

    float h[8];
    h[0] = fmaxf(dc * a0.x + dc2 * s0.x + b0.x, 0.f);
    h[1] = fmaxf(dc * a0.y + dc2 * s0.y + b0.y, 0.f);
    h[2] = fmaxf(dc * a0.z + dc2 * s0.z + b0.z, 0.f);
    h[3] = fmaxf(dc * a0.w + dc2 * s0.w + b0.w, 0.f);
    h[4] = fmaxf(dc * a1.x + dc2 * s1.x + b1.x, 0.f);
    h[5] = fmaxf(dc * a1.y + dc2 * s1.y + b1.y, 0.f);
    h[6] = fmaxf(dc * a1.z + dc2 * s1.z + b1.z, 0.f);
    h[7] = fmaxf(dc * a1.w + dc2 * s1.w + b1.w, 0.f);

    __nv_bfloat16 hi[8], lo[8];
#pragma unroll
    for (int i = 0; i < 8; i++) {
        hi[i] = __float2bfloat16(h[i]);
        lo[i] = __float2bfloat16(h[i] - __bfloat162float(hi[i]));
    }
    size_t o = (size_t)c * HC + off + q * 8;
    *(uint4*)(g_hcat_hi + o) = *(const uint4*)hi;
    *(uint4*)(g_hcat_lo + o) = *(const uint4*)lo;
}

// ---------------- log_softmax over padded logits (stride 64) --------------
__global__ void k_lsm(const float* __restrict__ blin, float* __restrict__ out) {
    int n = blockIdx.x * 256 + threadIdx.x;
    if (n >= Nn) return;
    float v[Cdim];
    float mx = -3.0e38f;
#pragma unroll
    for (int j = 0; j < Cdim; j++) {
        v[j] = g_lin[(size_t)n * 64 + j] + blin[j];
        mx = fmaxf(mx, v[j]);
    }
    float s = 0.f;
#pragma unroll
    for (int j = 0; j < Cdim; j++) s += expf(v[j] - mx);
    float lg = logf(s);
#pragma unroll
    for (int j = 0; j < Cdim; j++) out[(size_t)n * Cdim + j] = v[j] - mx - lg;
}

// ---------------- launch ---------------------------------------------------
static inline int nb(int n, int b) { return (n + b - 1) / b; }
#define GEMM_SMEM (2 * STAGE_BYTES + 1024)

extern "C" void kernel_launch(void* const* d_in, const int* in_sizes, int n_in,
                              void* d_out, int out_size) {
    const float* x    = (const float*)d_in[0];
    const int*   ei   = (const int*)d_in[1];
    const int*   rowi = ei;          // edge_index[0] = source
    const int*   coli = ei + Ed;     // edge_index[1] = target
    const float* W[6];
    const float* b[6];
    for (int i = 0; i < 6; i++) {
        W[i] = (const float*)d_in[2 + 2 * i];
        b[i] = (const float*)d_in[3 + 2 * i];
    }
    const float* Wlin = (const float*)d_in[14];
    const float* blin = (const float*)d_in[15];
    float* out = (float*)d_out;

    cudaFuncSetAttribute(k_gemm_mma, cudaFuncAttributeMaxDynamicSharedMemorySize, GEMM_SMEM);

    k_zero_deg<<<nb(Nn, 256), 256>>>();
    k_count<<<nb(Ed, 256), 256>>>(coli);
    k_dinv<<<nb(Nn, 256), 256>>>();
    k_scan1<<<NB_SCAN, 256>>>();
    k_scan2<<<1, 512>>>();
    k_scan3<<<nb(Nn, 256), 256>>>();
    k_build<<<nb(Ed, 256), 256>>>(rowi, coli);
    k_convx<<<nb(Nn * 128, 256), 256>>>(x);

    int gemm_grid = nb(Nn, 256);
    for (int i = 0; i < 6; i++) {
        int K   = Fdim + Hdim * i;        // 512,576,...,832
        int off = K;
        k_convW<<<nb(K * 64, 256), 256>>>(W[i], K);
        k_gemm_mma<<<gemm_grid, 256, GEMM_SMEM>>>(K);
        k_agg_fused<<<nb(Nn * 8, 256), 256>>>(b[i], off);
    }

    k_convWlin<<<nb(HC * 64, 256), 256>>>(Wlin);
    k_gemm_mma<<<gemm_grid, 256, GEMM_SMEM>>>(HC);
    k_lsm<<<nb(Nn, 256), 256>>>(blin, out);
}

// round 9
// speedup vs baseline: 1.0798x; 1.0798x over previous
#include <cuda_runtime.h>
#include <cuda_bf16.h>
#include <cstdint>

#define Nn   100000
#define Fdim 512
#define Hdim 64
#define Cdim 40
#define Ed   1600000
#define HC   896      // F + 6*H  (hcat width)
#define NB_SCAN 391   // ceil(Nn/256)

// ---------------- scratch (device globals; no allocation allowed) ----------
__device__ __nv_bfloat16 g_hcat_hi[(size_t)Nn * HC];  // 179 MB
__device__ __nv_bfloat16 g_hcat_lo[(size_t)Nn * HC];  // 179 MB
__device__ float g_lin[(size_t)Nn * Hdim];            // GEMM output (64 cols)
__device__ float g_dinv[Nn];
__device__ int   g_deg[Nn];
__device__ int   g_off[Nn];                           // CSR offsets (exclusive scan of deg)
__device__ int   g_cursor[Nn];
__device__ int   g_bsum[NB_SCAN];
__device__ int   g_esrc[Ed];                          // CSR: source node per edge slot
__device__ __nv_bfloat16 g_Wt_hi[64 * HC];            // weights transposed [n][k]
__device__ __nv_bfloat16 g_Wt_lo[64 * HC];

// ---------------- tiny PTX helpers ----------------------------------------
__device__ __forceinline__ uint32_t smem_u32(const void* p) {
    uint32_t a;
    asm("{ .reg .u64 t; cvta.to.shared.u64 t, %1; cvt.u32.u64 %0, t; }" : "=r"(a) : "l"(p));
    return a;
}
__device__ __forceinline__ uint32_t swz(uint32_t off) { return off ^ ((off >> 3) & 0x70); }

__device__ __forceinline__ void cp16(uint32_t dst, const void* src, int sz) {
    asm volatile("cp.async.cg.shared.global [%0], [%1], 16, %2;"
                 :: "r"(dst), "l"(src), "r"(sz) : "memory");
}
__device__ __forceinline__ void ldm_x4(uint32_t* r, uint32_t addr) {
    asm volatile("ldmatrix.sync.aligned.m8n8.x4.shared.b16 {%0,%1,%2,%3}, [%4];"
                 : "=r"(r[0]), "=r"(r[1]), "=r"(r[2]), "=r"(r[3]) : "r"(addr));
}
__device__ __forceinline__ void mma16816(float* d, const uint32_t* a, const uint32_t* b) {
    asm volatile("mma.sync.aligned.m16n8k16.row.col.f32.bf16.bf16.f32 "
                 "{%0,%1,%2,%3},{%4,%5,%6,%7},{%8,%9},{%0,%1,%2,%3};"
                 : "+f"(d[0]), "+f"(d[1]), "+f"(d[2]), "+f"(d[3])
                 : "r"(a[0]), "r"(a[1]), "r"(a[2]), "r"(a[3]), "r"(b[0]), "r"(b[1]));
}

// ---------------- degree / norm -------------------------------------------
__global__ void k_zero_deg() {
    int i = blockIdx.x * 256 + threadIdx.x;
    if (i < Nn) g_deg[i] = 0;
}
__global__ void k_count(const int* __restrict__ col) {
    int e = blockIdx.x * 256 + threadIdx.x;
    if (e < Ed) atomicAdd(&g_deg[col[e]], 1);
}
__global__ void k_dinv() {
    int i = blockIdx.x * 256 + threadIdx.x;
    if (i < Nn) g_dinv[i] = rsqrtf((float)(g_deg[i] + 1));  // +1 self loop
}

// ---------------- CSR build: scan + counting sort -------------------------
__global__ void k_scan1() {
    __shared__ int sh[256];
    int b = blockIdx.x, t = threadIdx.x;
    int i = b * 256 + t;
    int v = (i < Nn) ? g_deg[i] : 0;
    sh[t] = v;
    __syncthreads();
    int acc = v;
#pragma unroll
    for (int d = 1; d < 256; d <<= 1) {
        int u = (t >= d) ? sh[t - d] : 0;
        __syncthreads();
        acc += u;
        sh[t] = acc;
        __syncthreads();
    }
    if (i < Nn) g_off[i] = acc - v;
    if (t == 255) g_bsum[b] = acc;
}
__global__ void k_scan2() {
    __shared__ int sh[512];
    int t = threadIdx.x;
    int v = (t < NB_SCAN) ? g_bsum[t] : 0;
    sh[t] = v;
    __syncthreads();
    int acc = v;
#pragma unroll
    for (int d = 1; d < 512; d <<= 1) {
        int u = (t >= d) ? sh[t - d] : 0;
        __syncthreads();
        acc += u;
        sh[t] = acc;
        __syncthreads();
    }
    if (t < NB_SCAN) g_bsum[t] = acc - v;
}
__global__ void k_scan3() {
    int i = blockIdx.x * 256 + threadIdx.x;
    if (i >= Nn) return;
    int o = g_off[i] + g_bsum[i >> 8];
    g_off[i] = o;
    g_cursor[i] = o;
}
__global__ void k_build(const int* __restrict__ rowi, const int* __restrict__ coli) {
    int e = blockIdx.x * 256 + threadIdx.x;
    if (e >= Ed) return;
    int pos = atomicAdd(&g_cursor[coli[e]], 1);
    g_esrc[pos] = rowi[e];
}

// ---------------- convert x -> hcat hi/lo [:, 0:512] ----------------------
__global__ void k_convx(const float* __restrict__ x) {
    int idx = blockIdx.x * 256 + threadIdx.x;     // Nn*128 float4s
    if (idx >= Nn * 128) return;
    int n = idx >> 7, q = idx & 127;
    float4 v = ((const float4*)x)[(size_t)n * 128 + q];
    size_t o = (size_t)n * HC + q * 4;
    __nv_bfloat16 h0 = __float2bfloat16(v.x), h1 = __float2bfloat16(v.y);
    __nv_bfloat16 h2 = __float2bfloat16(v.z), h3 = __float2bfloat16(v.w);
    __nv_bfloat16 l0 = __float2bfloat16(v.x - __bfloat162float(h0));
    __nv_bfloat16 l1 = __float2bfloat16(v.y - __bfloat162float(h1));
    __nv_bfloat16 l2 = __float2bfloat16(v.z - __bfloat162float(h2));
    __nv_bfloat16 l3 = __float2bfloat16(v.w - __bfloat162float(h3));
    *(__nv_bfloat162*)(g_hcat_hi + o)     = __nv_bfloat162(h0, h1);
    *(__nv_bfloat162*)(g_hcat_hi + o + 2) = __nv_bfloat162(h2, h3);
    *(__nv_bfloat162*)(g_hcat_lo + o)     = __nv_bfloat162(l0, l1);
    *(__nv_bfloat162*)(g_hcat_lo + o + 2) = __nv_bfloat162(l2, l3);
}

// ---------------- weight conversion: W[K][64] -> Wt hi/lo [64][896] -------
__global__ void k_convW(const float* __restrict__ W, int K) {
    int idx = blockIdx.x * 256 + threadIdx.x;
    if (idx >= K * 64) return;
    int k = idx >> 6, n = idx & 63;
    float w = W[idx];
    __nv_bfloat16 h = __float2bfloat16(w);
    __nv_bfloat16 l = __float2bfloat16(w - __bfloat162float(h));
    g_Wt_hi[n * HC + k] = h;
    g_Wt_lo[n * HC + k] = l;
}
__global__ void k_convWlin(const float* __restrict__ Wlin) {
    int idx = blockIdx.x * 256 + threadIdx.x;     // 896*64
    if (idx >= HC * 64) return;
    int k = idx >> 6, n = idx & 63;
    float w = (n < Cdim) ? Wlin[k * Cdim + n] : 0.f;
    __nv_bfloat16 h = __float2bfloat16(w);
    __nv_bfloat16 l = __float2bfloat16(w - __bfloat162float(h));
    g_Wt_hi[n * HC + k] = h;
    g_Wt_lo[n * HC + k] = l;
}

// ---------------- mma.sync GEMM: g_lin[N,64] = hcat[:, :K] @ W ------------
// CTA: 128 rows x 64 cols, 256 threads / 8 warps (each warp 16x64).
// bf16 hi/lo, 3 products. K-chunks of 64, double-buffered, SW128.
#define STAGE_BYTES 49152
__global__ void __launch_bounds__(256, 2) k_gemm_mma(int K) {
    extern __shared__ char smem[];
    uint32_t sbase = smem_u32(smem);
    uint32_t data = (sbase + 1023) & ~1023u;

    int t = threadIdx.x, wid = t >> 5, lane = t & 31;
    int rowBase = blockIdx.x * 128;
    int m0 = wid * 16;

    float acc[8][4];
#pragma unroll
    for (int j = 0; j < 8; j++)
#pragma unroll
        for (int k = 0; k < 4; k++) acc[j][k] = 0.f;

    auto load_chunk = [&](int c, int s) {
        uint32_t sa = data + s * STAGE_BYTES;
        // A tiles: 128 rows x 64 k (128B/row), hi (16KB) + lo (16KB)
#pragma unroll
        for (int i = 0; i < 4; i++) {
            int idx = t + i * 256;           // 0..1023
            int r = idx >> 3, g = idx & 7;
            int gr = rowBase + r;
            int sz = (gr < Nn) ? 16 : 0;
            int grc = (gr < Nn) ? gr : (Nn - 1);
            size_t go = (size_t)grc * HC + c * 64 + g * 8;
            uint32_t d = sa + swz(r * 128 + g * 16);
            cp16(d, g_hcat_hi + go, sz);
            cp16(d + 16384, g_hcat_lo + go, sz);
        }
        // B tiles: 64 n-rows x 64 k, hi (8KB) + lo (8KB)
#pragma unroll
        for (int i = 0; i < 2; i++) {
            int idx = t + i * 256;           // 0..511
            int n = idx >> 3, g = idx & 7;
            size_t go = (size_t)n * HC + c * 64 + g * 8;
            uint32_t d = sa + 32768 + swz(n * 128 + g * 16);
            cp16(d, g_Wt_hi + go, 16);
            cp16(d + 8192, g_Wt_lo + go, 16);
        }
        asm volatile("cp.async.commit_group;" ::: "memory");
    };

    int nC = K / 64;
    load_chunk(0, 0);
    load_chunk(1, 1);

    for (int c = 0; c < nC; c++) {
        int s = c & 1;
        if (c + 1 < nC) asm volatile("cp.async.wait_group 1;" ::: "memory");
        else            asm volatile("cp.async.wait_group 0;" ::: "memory");
        __syncthreads();

        uint32_t sa = data + s * STAGE_BYTES;
#pragma unroll
        for (int ks = 0; ks < 4; ks++) {
            // A fragments: 1 m-tile (16x16), hi+lo
            uint32_t ahi[4], alo[4];
            {
                int row = m0 + (lane & 15);
                uint32_t off = swz(row * 128 + ks * 32 + (lane >> 4) * 16);
                ldm_x4(ahi, sa + off);
                ldm_x4(alo, sa + 16384 + off);
            }
            // B fragments: x4 loads 2 n-tiles (4 m8n8) at once
            uint32_t bhi[8][2], blo[8][2];
#pragma unroll
            for (int j2 = 0; j2 < 4; j2++) {
                int nr = j2 * 16 + ((lane >> 4) * 8) + (lane & 7);
                int kh = (lane >> 3) & 1;
                uint32_t off = swz(nr * 128 + ks * 32 + kh * 16);
                uint32_t tmp[4];
                ldm_x4(tmp, sa + 32768 + off);
                bhi[2 * j2][0] = tmp[0]; bhi[2 * j2][1] = tmp[1];
                bhi[2 * j2 + 1][0] = tmp[2]; bhi[2 * j2 + 1][1] = tmp[3];
                ldm_x4(tmp, sa + 40960 + off);
                blo[2 * j2][0] = tmp[0]; blo[2 * j2][1] = tmp[1];
                blo[2 * j2 + 1][0] = tmp[2]; blo[2 * j2 + 1][1] = tmp[3];
            }
#pragma unroll
            for (int j = 0; j < 8; j++) {
                mma16816(acc[j], ahi, bhi[j]);
                mma16816(acc[j], ahi, blo[j]);
                mma16816(acc[j], alo, bhi[j]);
            }
        }
        __syncthreads();
        if (c + 2 < nC) load_chunk(c + 2, s);
    }

    int rBase = rowBase + m0 + (lane >> 2);
    int cBase = (lane & 3) * 2;
#pragma unroll
    for (int j = 0; j < 8; j++) {
        int col = j * 8 + cBase;
        if (rBase < Nn)
            *(float2*)(g_lin + (size_t)rBase * 64 + col) = make_float2(acc[j][0], acc[j][1]);
        if (rBase + 8 < Nn)
            *(float2*)(g_lin + (size_t)(rBase + 8) * 64 + col) = make_float2(acc[j][2], acc[j][3]);
    }
}

// ---------------- fused CSR aggregate + self-loop + bias + relu + hi/lo ----
// 16 threads per node; thread q handles float4 q (fully coalesced rows).
__global__ void k_agg_fused(const float* __restrict__ bias, int off) {
    int gid = blockIdx.x * 256 + threadIdx.x;
    int c = gid >> 4;
    if (c >= Nn) return;
    int q = gid & 15;

    int e0 = g_off[c];
    int d  = g_deg[c];
    float4 a = make_float4(0.f, 0.f, 0.f, 0.f);
    for (int i = 0; i < d; i++) {
        int r = __ldg(&g_esrc[e0 + i]);
        float w = __ldg(&g_dinv[r]);
        float4 v = __ldg(((const float4*)(g_lin + (size_t)r * 64)) + q);
        a.x += w * v.x; a.y += w * v.y; a.z += w * v.z; a.w += w * v.w;
    }
    float dc = g_dinv[c];
    float dc2 = dc * dc;
    float4 s0 = __ldg(((const float4*)(g_lin + (size_t)c * 64)) + q);
    float4 b0 = ((const float4*)bias)[q];

    float h[4];
    h[0] = fmaxf(dc * a.x + dc2 * s0.x + b0.x, 0.f);
    h[1] = fmaxf(dc * a.y + dc2 * s0.y + b0.y, 0.f);
    h[2] = fmaxf(dc * a.z + dc2 * s0.z + b0.z, 0.f);
    h[3] = fmaxf(dc * a.w + dc2 * s0.w + b0.w, 0.f);

    __nv_bfloat16 hi[4], lo[4];
#pragma unroll
    for (int i = 0; i < 4; i++) {
        hi[i] = __float2bfloat16(h[i]);
        lo[i] = __float2bfloat16(h[i] - __bfloat162float(hi[i]));
    }
    size_t o = (size_t)c * HC + off + q * 4;
    *(uint2*)(g_hcat_hi + o) = *(const uint2*)hi;
    *(uint2*)(g_hcat_lo + o) = *(const uint2*)lo;
}

// ---------------- log_softmax over padded logits (stride 64) --------------
__global__ void k_lsm(const float* __restrict__ blin, float* __restrict__ out) {
    int n = blockIdx.x * 256 + threadIdx.x;
    if (n >= Nn) return;
    float v[Cdim];
    float mx = -3.0e38f;
#pragma unroll
    for (int j = 0; j < Cdim; j++) {
        v[j] = g_lin[(size_t)n * 64 + j] + blin[j];
        mx = fmaxf(mx, v[j]);
    }
    float s = 0.f;
#pragma unroll
    for (int j = 0; j < Cdim; j++) s += expf(v[j] - mx);
    float lg = logf(s);
#pragma unroll
    for (int j = 0; j < Cdim; j++) out[(size_t)n * Cdim + j] = v[j] - mx - lg;
}

// ---------------- launch ---------------------------------------------------
static inline int nb(int n, int b) { return (n + b - 1) / b; }
#define GEMM_SMEM (2 * STAGE_BYTES + 1024)

extern "C" void kernel_launch(void* const* d_in, const int* in_sizes, int n_in,
                              void* d_out, int out_size) {
    const float* x    = (const float*)d_in[0];
    const int*   ei   = (const int*)d_in[1];
    const int*   rowi = ei;          // edge_index[0] = source
    const int*   coli = ei + Ed;     // edge_index[1] = target
    const float* W[6];
    const float* b[6];
    for (int i = 0; i < 6; i++) {
        W[i] = (const float*)d_in[2 + 2 * i];
        b[i] = (const float*)d_in[3 + 2 * i];
    }
    const float* Wlin = (const float*)d_in[14];
    const float* blin = (const float*)d_in[15];
    float* out = (float*)d_out;

    cudaFuncSetAttribute(k_gemm_mma, cudaFuncAttributeMaxDynamicSharedMemorySize, GEMM_SMEM);

    k_zero_deg<<<nb(Nn, 256), 256>>>();
    k_count<<<nb(Ed, 256), 256>>>(coli);
    k_dinv<<<nb(Nn, 256), 256>>>();
    k_scan1<<<NB_SCAN, 256>>>();
    k_scan2<<<1, 512>>>();
    k_scan3<<<nb(Nn, 256), 256>>>();
    k_build<<<nb(Ed, 256), 256>>>(rowi, coli);
    k_convx<<<nb(Nn * 128, 256), 256>>>(x);

    int gemm_grid = nb(Nn, 128);
    for (int i = 0; i < 6; i++) {
        int K   = Fdim + Hdim * i;        // 512,576,...,832
        int off = K;
        k_convW<<<nb(K * 64, 256), 256>>>(W[i], K);
        k_gemm_mma<<<gemm_grid, 256, GEMM_SMEM>>>(K);
        k_agg_fused<<<nb(Nn * 16, 256), 256>>>(b[i], off);
    }

    k_convWlin<<<nb(HC * 64, 256), 256>>>(Wlin);
    k_gemm_mma<<<gemm_grid, 256, GEMM_SMEM>>>(HC);
    k_lsm<<<nb(Nn, 256), 256>>>(blin, out);
}

// round 10
// speedup vs baseline: 1.1561x; 1.0707x over previous
#include <cuda_runtime.h>
#include <cuda_bf16.h>
#include <cstdint>

#define Nn   100000
#define Fdim 512
#define Hdim 64
#define Cdim 40
#define Ed   1600000
#define HC   896      // F + 6*H  (hcat width)
#define NB_SCAN 391   // ceil(Nn/256)
#define WSLOT (64 * HC)

// ---------------- scratch (device globals; no allocation allowed) ----------
__device__ __nv_bfloat16 g_hcat_hi[(size_t)Nn * HC];  // 179 MB
__device__ __nv_bfloat16 g_hcat_lo[(size_t)Nn * HC];  // 179 MB
__device__ float g_lin[(size_t)Nn * Hdim];            // GEMM output (64 cols)
__device__ float g_dinv[Nn];
__device__ int   g_deg[Nn];
__device__ int   g_off[Nn];                           // CSR offsets
__device__ int   g_cursor[Nn];
__device__ int   g_bsum[NB_SCAN];
__device__ int   g_esrc[Ed];                          // CSR: source node per edge slot
__device__ __nv_bfloat16 g_WtA_hi[7 * WSLOT];         // all weights transposed [n][k]
__device__ __nv_bfloat16 g_WtA_lo[7 * WSLOT];

// ---------------- tiny PTX helpers ----------------------------------------
__device__ __forceinline__ uint32_t smem_u32(const void* p) {
    uint32_t a;
    asm("{ .reg .u64 t; cvta.to.shared.u64 t, %1; cvt.u32.u64 %0, t; }" : "=r"(a) : "l"(p));
    return a;
}
__device__ __forceinline__ uint32_t swz(uint32_t off) { return off ^ ((off >> 3) & 0x70); }

__device__ __forceinline__ void cp16(uint32_t dst, const void* src, int sz) {
    asm volatile("cp.async.cg.shared.global [%0], [%1], 16, %2;"
                 :: "r"(dst), "l"(src), "r"(sz) : "memory");
}
__device__ __forceinline__ void ldm_x4(uint32_t* r, uint32_t addr) {
    asm volatile("ldmatrix.sync.aligned.m8n8.x4.shared.b16 {%0,%1,%2,%3}, [%4];"
                 : "=r"(r[0]), "=r"(r[1]), "=r"(r[2]), "=r"(r[3]) : "r"(addr));
}
__device__ __forceinline__ void mma16816(float* d, const uint32_t* a, const uint32_t* b) {
    asm volatile("mma.sync.aligned.m16n8k16.row.col.f32.bf16.bf16.f32 "
                 "{%0,%1,%2,%3},{%4,%5,%6,%7},{%8,%9},{%0,%1,%2,%3};"
                 : "+f"(d[0]), "+f"(d[1]), "+f"(d[2]), "+f"(d[3])
                 : "r"(a[0]), "r"(a[1]), "r"(a[2]), "r"(a[3]), "r"(b[0]), "r"(b[1]));
}

// ---------------- degree / norm -------------------------------------------
__global__ void k_zero_deg() {
    int i = blockIdx.x * 256 + threadIdx.x;
    if (i < Nn) g_deg[i] = 0;
}
__global__ void k_count(const int* __restrict__ col) {
    int e = blockIdx.x * 256 + threadIdx.x;
    if (e < Ed) atomicAdd(&g_deg[col[e]], 1);
}
__global__ void k_dinv() {
    int i = blockIdx.x * 256 + threadIdx.x;
    if (i < Nn) g_dinv[i] = rsqrtf((float)(g_deg[i] + 1));  // +1 self loop
}

// ---------------- CSR build: scan + counting sort -------------------------
__global__ void k_scan1() {
    __shared__ int sh[256];
    int b = blockIdx.x, t = threadIdx.x;
    int i = b * 256 + t;
    int v = (i < Nn) ? g_deg[i] : 0;
    sh[t] = v;
    __syncthreads();
    int acc = v;
#pragma unroll
    for (int d = 1; d < 256; d <<= 1) {
        int u = (t >= d) ? sh[t - d] : 0;
        __syncthreads();
        acc += u;
        sh[t] = acc;
        __syncthreads();
    }
    if (i < Nn) g_off[i] = acc - v;
    if (t == 255) g_bsum[b] = acc;
}
__global__ void k_scan2() {
    __shared__ int sh[512];
    int t = threadIdx.x;
    int v = (t < NB_SCAN) ? g_bsum[t] : 0;
    sh[t] = v;
    __syncthreads();
    int acc = v;
#pragma unroll
    for (int d = 1; d < 512; d <<= 1) {
        int u = (t >= d) ? sh[t - d] : 0;
        __syncthreads();
        acc += u;
        sh[t] = acc;
        __syncthreads();
    }
    if (t < NB_SCAN) g_bsum[t] = acc - v;
}
__global__ void k_scan3() {
    int i = blockIdx.x * 256 + threadIdx.x;
    if (i >= Nn) return;
    int o = g_off[i] + g_bsum[i >> 8];
    g_off[i] = o;
    g_cursor[i] = o;
}
__global__ void k_build(const int* __restrict__ rowi, const int* __restrict__ coli) {
    int e = blockIdx.x * 256 + threadIdx.x;
    if (e >= Ed) return;
    int pos = atomicAdd(&g_cursor[coli[e]], 1);
    g_esrc[pos] = rowi[e];
}

// ---------------- convert x -> hcat hi/lo [:, 0:512] ----------------------
__global__ void k_convx(const float* __restrict__ x) {
    int idx = blockIdx.x * 256 + threadIdx.x;     // Nn*128 float4s
    if (idx >= Nn * 128) return;
    int n = idx >> 7, q = idx & 127;
    float4 v = ((const float4*)x)[(size_t)n * 128 + q];
    size_t o = (size_t)n * HC + q * 4;
    __nv_bfloat16 h0 = __float2bfloat16(v.x), h1 = __float2bfloat16(v.y);
    __nv_bfloat16 h2 = __float2bfloat16(v.z), h3 = __float2bfloat16(v.w);
    __nv_bfloat16 l0 = __float2bfloat16(v.x - __bfloat162float(h0));
    __nv_bfloat16 l1 = __float2bfloat16(v.y - __bfloat162float(h1));
    __nv_bfloat16 l2 = __float2bfloat16(v.z - __bfloat162float(h2));
    __nv_bfloat16 l3 = __float2bfloat16(v.w - __bfloat162float(h3));
    *(__nv_bfloat162*)(g_hcat_hi + o)     = __nv_bfloat162(h0, h1);
    *(__nv_bfloat162*)(g_hcat_hi + o + 2) = __nv_bfloat162(h2, h3);
    *(__nv_bfloat162*)(g_hcat_lo + o)     = __nv_bfloat162(l0, l1);
    *(__nv_bfloat162*)(g_hcat_lo + o + 2) = __nv_bfloat162(l2, l3);
}

// ---------------- convert ALL weights upfront -----------------------------
// layer l<6: W_l [K_l,64], K_l = 512+64*l. layer 6: Wlin [896,40] padded.
__global__ void k_convW_all(const float* __restrict__ W0, const float* __restrict__ W1,
                            const float* __restrict__ W2, const float* __restrict__ W3,
                            const float* __restrict__ W4, const float* __restrict__ W5,
                            const float* __restrict__ Wlin) {
    // prefix bases (elements = K_l*64): 0,32768,69632,110592,155648,204800,258048; end 315392
    const int base[8] = {0, 32768, 69632, 110592, 155648, 204800, 258048, 315392};
    const float* Ws[7] = {W0, W1, W2, W3, W4, W5, Wlin};
    int idx = blockIdx.x * 256 + threadIdx.x;
    if (idx >= 315392) return;
    int l = 0;
#pragma unroll
    for (int j = 1; j < 7; j++) if (idx >= base[j]) l = j;
    int e = idx - base[l];
    int k = e >> 6, n = e & 63;
    float w;
    if (l < 6) w = Ws[l][k * 64 + n];
    else       w = (n < Cdim) ? Ws[6][k * Cdim + n] : 0.f;
    __nv_bfloat16 h = __float2bfloat16(w);
    __nv_bfloat16 lo = __float2bfloat16(w - __bfloat162float(h));
    size_t o = (size_t)l * WSLOT + (size_t)n * HC + k;
    g_WtA_hi[o] = h;
    g_WtA_lo[o] = lo;
}

// ---------------- mma.sync GEMM: g_lin[N,64] = hcat[:, :K] @ W ------------
// CTA: 128 rows x 64 cols, 256 threads / 8 warps (each warp 16x64).
// bf16 hi/lo, 3 products. K-chunks of 64, double-buffered, SW128.
// mode 0: write g_lin.  mode 1: fused +blin, log_softmax, write out[N,40].
#define STAGE_BYTES 49152
__global__ void __launch_bounds__(256, 2) k_gemm_mma(int K, int wslot, int mode,
                                                     const float* __restrict__ blin,
                                                     float* __restrict__ out) {
    extern __shared__ char smem[];
    uint32_t sbase = smem_u32(smem);
    uint32_t data = (sbase + 1023) & ~1023u;

    int t = threadIdx.x, wid = t >> 5, lane = t & 31;
    int rowBase = blockIdx.x * 128;
    int m0 = wid * 16;
    const __nv_bfloat16* Whi = g_WtA_hi + (size_t)wslot * WSLOT;
    const __nv_bfloat16* Wlo = g_WtA_lo + (size_t)wslot * WSLOT;

    float acc[8][4];
#pragma unroll
    for (int j = 0; j < 8; j++)
#pragma unroll
        for (int k = 0; k < 4; k++) acc[j][k] = 0.f;

    auto load_chunk = [&](int c, int s) {
        uint32_t sa = data + s * STAGE_BYTES;
#pragma unroll
        for (int i = 0; i < 4; i++) {
            int idx = t + i * 256;           // 0..1023
            int r = idx >> 3, g = idx & 7;
            int gr = rowBase + r;
            int sz = (gr < Nn) ? 16 : 0;
            int grc = (gr < Nn) ? gr : (Nn - 1);
            size_t go = (size_t)grc * HC + c * 64 + g * 8;
            uint32_t d = sa + swz(r * 128 + g * 16);
            cp16(d, g_hcat_hi + go, sz);
            cp16(d + 16384, g_hcat_lo + go, sz);
        }
#pragma unroll
        for (int i = 0; i < 2; i++) {
            int idx = t + i * 256;           // 0..511
            int n = idx >> 3, g = idx & 7;
            size_t go = (size_t)n * HC + c * 64 + g * 8;
            uint32_t d = sa + 32768 + swz(n * 128 + g * 16);
            cp16(d, Whi + go, 16);
            cp16(d + 8192, Wlo + go, 16);
        }
        asm volatile("cp.async.commit_group;" ::: "memory");
    };

    int nC = K / 64;
    load_chunk(0, 0);
    load_chunk(1, 1);

    for (int c = 0; c < nC; c++) {
        int s = c & 1;
        if (c + 1 < nC) asm volatile("cp.async.wait_group 1;" ::: "memory");
        else            asm volatile("cp.async.wait_group 0;" ::: "memory");
        __syncthreads();

        uint32_t sa = data + s * STAGE_BYTES;
#pragma unroll
        for (int ks = 0; ks < 4; ks++) {
            uint32_t ahi[4], alo[4];
            {
                int row = m0 + (lane & 15);
                uint32_t off = swz(row * 128 + ks * 32 + (lane >> 4) * 16);
                ldm_x4(ahi, sa + off);
                ldm_x4(alo, sa + 16384 + off);
            }
            uint32_t bhi[8][2], blo[8][2];
#pragma unroll
            for (int j2 = 0; j2 < 4; j2++) {
                int nr = j2 * 16 + ((lane >> 4) * 8) + (lane & 7);
                int kh = (lane >> 3) & 1;
                uint32_t off = swz(nr * 128 + ks * 32 + kh * 16);
                uint32_t tmp[4];
                ldm_x4(tmp, sa + 32768 + off);
                bhi[2 * j2][0] = tmp[0]; bhi[2 * j2][1] = tmp[1];
                bhi[2 * j2 + 1][0] = tmp[2]; bhi[2 * j2 + 1][1] = tmp[3];
                ldm_x4(tmp, sa + 40960 + off);
                blo[2 * j2][0] = tmp[0]; blo[2 * j2][1] = tmp[1];
                blo[2 * j2 + 1][0] = tmp[2]; blo[2 * j2 + 1][1] = tmp[3];
            }
#pragma unroll
            for (int j = 0; j < 8; j++) {
                mma16816(acc[j], ahi, bhi[j]);
                mma16816(acc[j], ahi, blo[j]);
                mma16816(acc[j], alo, bhi[j]);
            }
        }
        __syncthreads();
        if (c + 2 < nC) load_chunk(c + 2, s);
    }

    int rBase = rowBase + m0 + (lane >> 2);
    int cBase = (lane & 3) * 2;

    if (mode == 0) {
#pragma unroll
        for (int j = 0; j < 8; j++) {
            int col = j * 8 + cBase;
            if (rBase < Nn)
                *(float2*)(g_lin + (size_t)rBase * 64 + col) = make_float2(acc[j][0], acc[j][1]);
            if (rBase + 8 < Nn)
                *(float2*)(g_lin + (size_t)(rBase + 8) * 64 + col) = make_float2(acc[j][2], acc[j][3]);
        }
    } else {
        // fused bias + log_softmax over valid cols 0..39 (j = 0..4 per thread).
        // rows rBase (vals 0,1) and rBase+8 (vals 2,3); each row lives in one
        // lane-quad (lanes 4a..4a+3) -> reduce via shfl_xor 1,2.
        float v0[10], v1[10];
        float mx0 = -3.0e38f, mx1 = -3.0e38f;
#pragma unroll
        for (int j = 0; j < 5; j++) {
            int col = j * 8 + cBase;
            float b0 = __ldg(&blin[col]), b1 = __ldg(&blin[col + 1]);
            v0[2 * j]     = acc[j][0] + b0;
            v0[2 * j + 1] = acc[j][1] + b1;
            v1[2 * j]     = acc[j][2] + b0;
            v1[2 * j + 1] = acc[j][3] + b1;
            mx0 = fmaxf(mx0, fmaxf(v0[2 * j], v0[2 * j + 1]));
            mx1 = fmaxf(mx1, fmaxf(v1[2 * j], v1[2 * j + 1]));
        }
        mx0 = fmaxf(mx0, __shfl_xor_sync(0xffffffffu, mx0, 1));
        mx0 = fmaxf(mx0, __shfl_xor_sync(0xffffffffu, mx0, 2));
        mx1 = fmaxf(mx1, __shfl_xor_sync(0xffffffffu, mx1, 1));
        mx1 = fmaxf(mx1, __shfl_xor_sync(0xffffffffu, mx1, 2));
        float s0 = 0.f, s1 = 0.f;
#pragma unroll
        for (int j = 0; j < 10; j++) {
            s0 += expf(v0[j] - mx0);
            s1 += expf(v1[j] - mx1);
        }
        s0 += __shfl_xor_sync(0xffffffffu, s0, 1);
        s0 += __shfl_xor_sync(0xffffffffu, s0, 2);
        s1 += __shfl_xor_sync(0xffffffffu, s1, 1);
        s1 += __shfl_xor_sync(0xffffffffu, s1, 2);
        float lg0 = mx0 + logf(s0), lg1 = mx1 + logf(s1);
#pragma unroll
        for (int j = 0; j < 5; j++) {
            int col = j * 8 + cBase;
            if (rBase < Nn)
                *(float2*)(out + (size_t)rBase * Cdim + col) =
                    make_float2(v0[2 * j] - lg0, v0[2 * j + 1] - lg0);
            if (rBase + 8 < Nn)
                *(float2*)(out + (size_t)(rBase + 8) * Cdim + col) =
                    make_float2(v1[2 * j] - lg1, v1[2 * j + 1] - lg1);
        }
    }
}

// ---------------- fused CSR aggregate + self-loop + bias + relu + hi/lo ----
// 16 threads per node; thread q handles float4 q (fully coalesced rows).
__global__ void k_agg_fused(const float* __restrict__ bias, int off) {
    int gid = blockIdx.x * 256 + threadIdx.x;
    int c = gid >> 4;
    if (c >= Nn) return;
    int q = gid & 15;

    int e0 = g_off[c];
    int d  = g_deg[c];
    float4 a = make_float4(0.f, 0.f, 0.f, 0.f);
    for (int i = 0; i < d; i++) {
        int r = __ldg(&g_esrc[e0 + i]);
        float w = __ldg(&g_dinv[r]);
        float4 v = __ldg(((const float4*)(g_lin + (size_t)r * 64)) + q);
        a.x += w * v.x; a.y += w * v.y; a.z += w * v.z; a.w += w * v.w;
    }
    float dc = g_dinv[c];
    float dc2 = dc * dc;
    float4 s0 = __ldg(((const float4*)(g_lin + (size_t)c * 64)) + q);
    float4 b0 = ((const float4*)bias)[q];

    float h[4];
    h[0] = fmaxf(dc * a.x + dc2 * s0.x + b0.x, 0.f);
    h[1] = fmaxf(dc * a.y + dc2 * s0.y + b0.y, 0.f);
    h[2] = fmaxf(dc * a.z + dc2 * s0.z + b0.z, 0.f);
    h[3] = fmaxf(dc * a.w + dc2 * s0.w + b0.w, 0.f);

    __nv_bfloat16 hi[4], lo[4];
#pragma unroll
    for (int i = 0; i < 4; i++) {
        hi[i] = __float2bfloat16(h[i]);
        lo[i] = __float2bfloat16(h[i] - __bfloat162float(hi[i]));
    }
    size_t o = (size_t)c * HC + off + q * 4;
    *(uint2*)(g_hcat_hi + o) = *(const uint2*)hi;
    *(uint2*)(g_hcat_lo + o) = *(const uint2*)lo;
}

// ---------------- launch ---------------------------------------------------
static inline int nb(int n, int b) { return (n + b - 1) / b; }
#define GEMM_SMEM (2 * STAGE_BYTES + 1024)

extern "C" void kernel_launch(void* const* d_in, const int* in_sizes, int n_in,
                              void* d_out, int out_size) {
    const float* x    = (const float*)d_in[0];
    const int*   ei   = (const int*)d_in[1];
    const int*   rowi = ei;          // edge_index[0] = source
    const int*   coli = ei + Ed;     // edge_index[1] = target
    const float* W[6];
    const float* b[6];
    for (int i = 0; i < 6; i++) {
        W[i] = (const float*)d_in[2 + 2 * i];
        b[i] = (const float*)d_in[3 + 2 * i];
    }
    const float* Wlin = (const float*)d_in[14];
    const float* blin = (const float*)d_in[15];
    float* out = (float*)d_out;

    cudaFuncSetAttribute(k_gemm_mma, cudaFuncAttributeMaxDynamicSharedMemorySize, GEMM_SMEM);

    k_zero_deg<<<nb(Nn, 256), 256>>>();
    k_count<<<nb(Ed, 256), 256>>>(coli);
    k_dinv<<<nb(Nn, 256), 256>>>();
    k_scan1<<<NB_SCAN, 256>>>();
    k_scan2<<<1, 512>>>();
    k_scan3<<<nb(Nn, 256), 256>>>();
    k_build<<<nb(Ed, 256), 256>>>(rowi, coli);
    k_convx<<<nb(Nn * 128, 256), 256>>>(x);
    k_convW_all<<<nb(315392, 256), 256>>>(W[0], W[1], W[2], W[3], W[4], W[5], Wlin);

    int gemm_grid = nb(Nn, 128);
    for (int i = 0; i < 6; i++) {
        int K   = Fdim + Hdim * i;        // 512,576,...,832
        int off = K;
        k_gemm_mma<<<gemm_grid, 256, GEMM_SMEM>>>(K, i, 0, nullptr, nullptr);
        k_agg_fused<<<nb(Nn * 16, 256), 256>>>(b[i], off);
    }

    k_gemm_mma<<<gemm_grid, 256, GEMM_SMEM>>>(HC, 6, 1, blin, out);
}

// round 11
// speedup vs baseline: 1.3929x; 1.2048x over previous
#include <cuda_runtime.h>
#include <cuda_fp16.h>
#include <cstdint>

#define Nn   100000
#define Fdim 512
#define Hdim 64
#define Cdim 40
#define Ed   1600000
#define HC   896      // F + 6*H  (hcat width)
#define NB_SCAN 391   // ceil(Nn/256)
#define WSLOT (64 * HC)

// ---------------- scratch (device globals; no allocation allowed) ----------
__device__ __half g_hcat[(size_t)Nn * HC];            // 179 MB, single fp16
__device__ float g_lin[(size_t)Nn * Hdim];            // GEMM output (64 cols)
__device__ float g_dinv[Nn];
__device__ int   g_deg[Nn];
__device__ int   g_off[Nn];                           // CSR offsets
__device__ int   g_cursor[Nn];
__device__ int   g_bsum[NB_SCAN];
__device__ int   g_esrc[Ed];                          // CSR: source node per edge slot
__device__ __half g_WtA_hi[7 * WSLOT];                // weights transposed [n][k], fp16 hi
__device__ __half g_WtA_lo[7 * WSLOT];                // fp16 residual

// ---------------- tiny PTX helpers ----------------------------------------
__device__ __forceinline__ uint32_t smem_u32(const void* p) {
    uint32_t a;
    asm("{ .reg .u64 t; cvta.to.shared.u64 t, %1; cvt.u32.u64 %0, t; }" : "=r"(a) : "l"(p));
    return a;
}
__device__ __forceinline__ uint32_t swz(uint32_t off) { return off ^ ((off >> 3) & 0x70); }

__device__ __forceinline__ void cp16(uint32_t dst, const void* src, int sz) {
    asm volatile("cp.async.cg.shared.global [%0], [%1], 16, %2;"
                 :: "r"(dst), "l"(src), "r"(sz) : "memory");
}
__device__ __forceinline__ void ldm_x4(uint32_t* r, uint32_t addr) {
    asm volatile("ldmatrix.sync.aligned.m8n8.x4.shared.b16 {%0,%1,%2,%3}, [%4];"
                 : "=r"(r[0]), "=r"(r[1]), "=r"(r[2]), "=r"(r[3]) : "r"(addr));
}
__device__ __forceinline__ void mma16816(float* d, const uint32_t* a, const uint32_t* b) {
    asm volatile("mma.sync.aligned.m16n8k16.row.col.f32.f16.f16.f32 "
                 "{%0,%1,%2,%3},{%4,%5,%6,%7},{%8,%9},{%0,%1,%2,%3};"
                 : "+f"(d[0]), "+f"(d[1]), "+f"(d[2]), "+f"(d[3])
                 : "r"(a[0]), "r"(a[1]), "r"(a[2]), "r"(a[3]), "r"(b[0]), "r"(b[1]));
}

// ---------------- degree / norm -------------------------------------------
__global__ void k_zero_deg() {
    int i = blockIdx.x * 256 + threadIdx.x;
    if (i < Nn) g_deg[i] = 0;
}
__global__ void k_count(const int* __restrict__ col) {
    int e = blockIdx.x * 256 + threadIdx.x;
    if (e < Ed) atomicAdd(&g_deg[col[e]], 1);
}
__global__ void k_dinv() {
    int i = blockIdx.x * 256 + threadIdx.x;
    if (i < Nn) g_dinv[i] = rsqrtf((float)(g_deg[i] + 1));  // +1 self loop
}

// ---------------- CSR build: scan + counting sort -------------------------
__global__ void k_scan1() {
    __shared__ int sh[256];
    int b = blockIdx.x, t = threadIdx.x;
    int i = b * 256 + t;
    int v = (i < Nn) ? g_deg[i] : 0;
    sh[t] = v;
    __syncthreads();
    int acc = v;
#pragma unroll
    for (int d = 1; d < 256; d <<= 1) {
        int u = (t >= d) ? sh[t - d] : 0;
        __syncthreads();
        acc += u;
        sh[t] = acc;
        __syncthreads();
    }
    if (i < Nn) g_off[i] = acc - v;
    if (t == 255) g_bsum[b] = acc;
}
__global__ void k_scan2() {
    __shared__ int sh[512];
    int t = threadIdx.x;
    int v = (t < NB_SCAN) ? g_bsum[t] : 0;
    sh[t] = v;
    __syncthreads();
    int acc = v;
#pragma unroll
    for (int d = 1; d < 512; d <<= 1) {
        int u = (t >= d) ? sh[t - d] : 0;
        __syncthreads();
        acc += u;
        sh[t] = acc;
        __syncthreads();
    }
    if (t < NB_SCAN) g_bsum[t] = acc - v;
}
__global__ void k_scan3() {
    int i = blockIdx.x * 256 + threadIdx.x;
    if (i >= Nn) return;
    int o = g_off[i] + g_bsum[i >> 8];
    g_off[i] = o;
    g_cursor[i] = o;
}
__global__ void k_build(const int* __restrict__ rowi, const int* __restrict__ coli) {
    int e = blockIdx.x * 256 + threadIdx.x;
    if (e >= Ed) return;
    int pos = atomicAdd(&g_cursor[coli[e]], 1);
    g_esrc[pos] = rowi[e];
}

// ---------------- convert x -> hcat fp16 [:, 0:512] -----------------------
__global__ void k_convx(const float* __restrict__ x) {
    int idx = blockIdx.x * 256 + threadIdx.x;     // Nn*128 float4s
    if (idx >= Nn * 128) return;
    int n = idx >> 7, q = idx & 127;
    float4 v = ((const float4*)x)[(size_t)n * 128 + q];
    __half h[4];
    h[0] = __float2half(v.x); h[1] = __float2half(v.y);
    h[2] = __float2half(v.z); h[3] = __float2half(v.w);
    *(uint2*)(g_hcat + (size_t)n * HC + q * 4) = *(const uint2*)h;
}

// ---------------- convert ALL weights upfront (fp16 hi/lo) ----------------
__global__ void k_convW_all(const float* __restrict__ W0, const float* __restrict__ W1,
                            const float* __restrict__ W2, const float* __restrict__ W3,
                            const float* __restrict__ W4, const float* __restrict__ W5,
                            const float* __restrict__ Wlin) {
    const int base[8] = {0, 32768, 69632, 110592, 155648, 204800, 258048, 315392};
    const float* Ws[7] = {W0, W1, W2, W3, W4, W5, Wlin};
    int idx = blockIdx.x * 256 + threadIdx.x;
    if (idx >= 315392) return;
    int l = 0;
#pragma unroll
    for (int j = 1; j < 7; j++) if (idx >= base[j]) l = j;
    int e = idx - base[l];
    int k = e >> 6, n = e & 63;
    float w;
    if (l < 6) w = Ws[l][k * 64 + n];
    else       w = (n < Cdim) ? Ws[6][k * Cdim + n] : 0.f;
    __half h = __float2half(w);
    __half lo = __float2half(w - __half2float(h));
    size_t o = (size_t)l * WSLOT + (size_t)n * HC + k;
    g_WtA_hi[o] = h;
    g_WtA_lo[o] = lo;
}

// ---------------- mma.sync GEMM: g_lin[N,64] = hcat[:, :K] @ W ------------
// CTA: 128 rows x 64 cols, 256 threads / 8 warps (each warp 16x64).
// A single fp16; B fp16 hi/lo (2 products). K-chunks of 64, double-buffered.
// Stage: A [0,16K) Bhi [16K,24K) Blo [24K,32K).  SW128, 128B rows.
// mode 0: write g_lin.  mode 1: fused +blin, log_softmax, write out[N,40].
#define STAGE_BYTES 32768
__global__ void __launch_bounds__(256, 3) k_gemm_mma(int K, int wslot, int mode,
                                                     const float* __restrict__ blin,
                                                     float* __restrict__ out) {
    extern __shared__ char smem[];
    uint32_t sbase = smem_u32(smem);
    uint32_t data = (sbase + 1023) & ~1023u;

    int t = threadIdx.x, wid = t >> 5, lane = t & 31;
    int rowBase = blockIdx.x * 128;
    int m0 = wid * 16;
    const __half* Whi = g_WtA_hi + (size_t)wslot * WSLOT;
    const __half* Wlo = g_WtA_lo + (size_t)wslot * WSLOT;

    float acc[8][4];
#pragma unroll
    for (int j = 0; j < 8; j++)
#pragma unroll
        for (int k = 0; k < 4; k++) acc[j][k] = 0.f;

    auto load_chunk = [&](int c, int s) {
        uint32_t sa = data + s * STAGE_BYTES;
        // A: 128 rows x 64 k (128B/row) = 1024 cp16, 4 per thread
#pragma unroll
        for (int i = 0; i < 4; i++) {
            int idx = t + i * 256;           // 0..1023
            int r = idx >> 3, g = idx & 7;
            int gr = rowBase + r;
            int sz = (gr < Nn) ? 16 : 0;
            int grc = (gr < Nn) ? gr : (Nn - 1);
            size_t go = (size_t)grc * HC + c * 64 + g * 8;
            cp16(sa + swz(r * 128 + g * 16), g_hcat + go, sz);
        }
        // B: 64 n-rows x 64 k, hi (8KB) + lo (8KB) = 512 cp16 each pair
#pragma unroll
        for (int i = 0; i < 2; i++) {
            int idx = t + i * 256;           // 0..511
            int n = idx >> 3, g = idx & 7;
            size_t go = (size_t)n * HC + c * 64 + g * 8;
            uint32_t d = sa + 16384 + swz(n * 128 + g * 16);
            cp16(d, Whi + go, 16);
            cp16(d + 8192, Wlo + go, 16);
        }
        asm volatile("cp.async.commit_group;" ::: "memory");
    };

    int nC = K / 64;
    load_chunk(0, 0);
    load_chunk(1, 1);

    for (int c = 0; c < nC; c++) {
        int s = c & 1;
        if (c + 1 < nC) asm volatile("cp.async.wait_group 1;" ::: "memory");
        else            asm volatile("cp.async.wait_group 0;" ::: "memory");
        __syncthreads();

        uint32_t sa = data + s * STAGE_BYTES;
#pragma unroll
        for (int ks = 0; ks < 4; ks++) {
            // A fragment: 1 m-tile (16x16)
            uint32_t a[4];
            {
                int row = m0 + (lane & 15);
                uint32_t off = swz(row * 128 + ks * 32 + (lane >> 4) * 16);
                ldm_x4(a, sa + off);
            }
            // B fragments: x4 loads 2 n-tiles at once, hi+lo
            uint32_t bhi[8][2], blo[8][2];
#pragma unroll
            for (int j2 = 0; j2 < 4; j2++) {
                int nr = j2 * 16 + ((lane >> 4) * 8) + (lane & 7);
                int kh = (lane >> 3) & 1;
                uint32_t off = swz(nr * 128 + ks * 32 + kh * 16);
                uint32_t tmp[4];
                ldm_x4(tmp, sa + 16384 + off);
                bhi[2 * j2][0] = tmp[0]; bhi[2 * j2][1] = tmp[1];
                bhi[2 * j2 + 1][0] = tmp[2]; bhi[2 * j2 + 1][1] = tmp[3];
                ldm_x4(tmp, sa + 24576 + off);
                blo[2 * j2][0] = tmp[0]; blo[2 * j2][1] = tmp[1];
                blo[2 * j2 + 1][0] = tmp[2]; blo[2 * j2 + 1][1] = tmp[3];
            }
#pragma unroll
            for (int j = 0; j < 8; j++) {
                mma16816(acc[j], a, bhi[j]);
                mma16816(acc[j], a, blo[j]);
            }
        }
        __syncthreads();
        if (c + 2 < nC) load_chunk(c + 2, s);
    }

    int rBase = rowBase + m0 + (lane >> 2);
    int cBase = (lane & 3) * 2;

    if (mode == 0) {
#pragma unroll
        for (int j = 0; j < 8; j++) {
            int col = j * 8 + cBase;
            if (rBase < Nn)
                *(float2*)(g_lin + (size_t)rBase * 64 + col) = make_float2(acc[j][0], acc[j][1]);
            if (rBase + 8 < Nn)
                *(float2*)(g_lin + (size_t)(rBase + 8) * 64 + col) = make_float2(acc[j][2], acc[j][3]);
        }
    } else {
        // fused bias + log_softmax over valid cols 0..39 (j = 0..4 per thread).
        float v0[10], v1[10];
        float mx0 = -3.0e38f, mx1 = -3.0e38f;
#pragma unroll
        for (int j = 0; j < 5; j++) {
            int col = j * 8 + cBase;
            float b0 = __ldg(&blin[col]), b1 = __ldg(&blin[col + 1]);
            v0[2 * j]     = acc[j][0] + b0;
            v0[2 * j + 1] = acc[j][1] + b1;
            v1[2 * j]     = acc[j][2] + b0;
            v1[2 * j + 1] = acc[j][3] + b1;
            mx0 = fmaxf(mx0, fmaxf(v0[2 * j], v0[2 * j + 1]));
            mx1 = fmaxf(mx1, fmaxf(v1[2 * j], v1[2 * j + 1]));
        }
        mx0 = fmaxf(mx0, __shfl_xor_sync(0xffffffffu, mx0, 1));
        mx0 = fmaxf(mx0, __shfl_xor_sync(0xffffffffu, mx0, 2));
        mx1 = fmaxf(mx1, __shfl_xor_sync(0xffffffffu, mx1, 1));
        mx1 = fmaxf(mx1, __shfl_xor_sync(0xffffffffu, mx1, 2));
        float s0 = 0.f, s1 = 0.f;
#pragma unroll
        for (int j = 0; j < 10; j++) {
            s0 += expf(v0[j] - mx0);
            s1 += expf(v1[j] - mx1);
        }
        s0 += __shfl_xor_sync(0xffffffffu, s0, 1);
        s0 += __shfl_xor_sync(0xffffffffu, s0, 2);
        s1 += __shfl_xor_sync(0xffffffffu, s1, 1);
        s1 += __shfl_xor_sync(0xffffffffu, s1, 2);
        float lg0 = mx0 + logf(s0), lg1 = mx1 + logf(s1);
#pragma unroll
        for (int j = 0; j < 5; j++) {
            int col = j * 8 + cBase;
            if (rBase < Nn)
                *(float2*)(out + (size_t)rBase * Cdim + col) =
                    make_float2(v0[2 * j] - lg0, v0[2 * j + 1] - lg0);
            if (rBase + 8 < Nn)
                *(float2*)(out + (size_t)(rBase + 8) * Cdim + col) =
                    make_float2(v1[2 * j] - lg1, v1[2 * j + 1] - lg1);
        }
    }
}

// ---------------- fused CSR aggregate + self-loop + bias + relu -> fp16 ----
// 16 threads per node; thread q handles float4 q (fully coalesced rows).
__global__ void k_agg_fused(const float* __restrict__ bias, int off) {
    int gid = blockIdx.x * 256 + threadIdx.x;
    int c = gid >> 4;
    if (c >= Nn) return;
    int q = gid & 15;

    int e0 = g_off[c];
    int d  = g_deg[c];
    float4 a = make_float4(0.f, 0.f, 0.f, 0.f);
    for (int i = 0; i < d; i++) {
        int r = __ldg(&g_esrc[e0 + i]);
        float w = __ldg(&g_dinv[r]);
        float4 v = __ldg(((const float4*)(g_lin + (size_t)r * 64)) + q);
        a.x += w * v.x; a.y += w * v.y; a.z += w * v.z; a.w += w * v.w;
    }
    float dc = g_dinv[c];
    float dc2 = dc * dc;
    float4 s0 = __ldg(((const float4*)(g_lin + (size_t)c * 64)) + q);
    float4 b0 = ((const float4*)bias)[q];

    __half h[4];
    h[0] = __float2half(fmaxf(dc * a.x + dc2 * s0.x + b0.x, 0.f));
    h[1] = __float2half(fmaxf(dc * a.y + dc2 * s0.y + b0.y, 0.f));
    h[2] = __float2half(fmaxf(dc * a.z + dc2 * s0.z + b0.z, 0.f));
    h[3] = __float2half(fmaxf(dc * a.w + dc2 * s0.w + b0.w, 0.f));
    *(uint2*)(g_hcat + (size_t)c * HC + off + q * 4) = *(const uint2*)h;
}

// ---------------- launch ---------------------------------------------------
static inline int nb(int n, int b) { return (n + b - 1) / b; }
#define GEMM_SMEM (2 * STAGE_BYTES + 1024)

extern "C" void kernel_launch(void* const* d_in, const int* in_sizes, int n_in,
                              void* d_out, int out_size) {
    const float* x    = (const float*)d_in[0];
    const int*   ei   = (const int*)d_in[1];
    const int*   rowi = ei;          // edge_index[0] = source
    const int*   coli = ei + Ed;     // edge_index[1] = target
    const float* W[6];
    const float* b[6];
    for (int i = 0; i < 6; i++) {
        W[i] = (const float*)d_in[2 + 2 * i];
        b[i] = (const float*)d_in[3 + 2 * i];
    }
    const float* Wlin = (const float*)d_in[14];
    const float* blin = (const float*)d_in[15];
    float* out = (float*)d_out;

    cudaFuncSetAttribute(k_gemm_mma, cudaFuncAttributeMaxDynamicSharedMemorySize, GEMM_SMEM);

    k_zero_deg<<<nb(Nn, 256), 256>>>();
    k_count<<<nb(Ed, 256), 256>>>(coli);
    k_dinv<<<nb(Nn, 256), 256>>>();
    k_scan1<<<NB_SCAN, 256>>>();
    k_scan2<<<1, 512>>>();
    k_scan3<<<nb(Nn, 256), 256>>>();
    k_build<<<nb(Ed, 256), 256>>>(rowi, coli);
    k_convx<<<nb(Nn * 128, 256), 256>>>(x);
    k_convW_all<<<nb(315392, 256), 256>>>(W[0], W[1], W[2], W[3], W[4], W[5], Wlin);

    int gemm_grid = nb(Nn, 128);
    for (int i = 0; i < 6; i++) {
        int K   = Fdim + Hdim * i;        // 512,576,...,832
        int off = K;
        k_gemm_mma<<<gemm_grid, 256, GEMM_SMEM>>>(K, i, 0, nullptr, nullptr);
        k_agg_fused<<<nb(Nn * 16, 256), 256>>>(b[i], off);
    }

    k_gemm_mma<<<gemm_grid, 256, GEMM_SMEM>>>(HC, 6, 1, blin, out);
}

// round 12
// speedup vs baseline: 1.5897x; 1.1413x over previous
#include <cuda_runtime.h>
#include <cuda_fp16.h>
#include <cstdint>

#define Nn   100000
#define Fdim 512
#define Hdim 64
#define Cdim 40
#define Ed   1600000
#define HC   896      // F + 6*H  (hcat width)
#define NB_SCAN 391   // ceil(Nn/256)
#define WSLOT (64 * HC)

// ---------------- scratch (device globals; no allocation allowed) ----------
__device__ __half g_hcat[(size_t)Nn * HC];            // 179 MB, fp16
__device__ float g_lin[(size_t)Nn * Hdim];            // GEMM output (64 cols)
__device__ float g_dinv[Nn];
__device__ int   g_deg[Nn];
__device__ int   g_off[Nn];                           // CSR offsets
__device__ int   g_cursor[Nn];
__device__ int   g_bsum[NB_SCAN];
__device__ int   g_esrc[Ed];                          // CSR: source node per edge slot
__device__ __half g_WtA[7 * WSLOT];                   // weights transposed [n][k], fp16

// ---------------- tiny PTX helpers ----------------------------------------
__device__ __forceinline__ uint32_t smem_u32(const void* p) {
    uint32_t a;
    asm("{ .reg .u64 t; cvta.to.shared.u64 t, %1; cvt.u32.u64 %0, t; }" : "=r"(a) : "l"(p));
    return a;
}
__device__ __forceinline__ uint32_t swz(uint32_t off) { return off ^ ((off >> 3) & 0x70); }

__device__ __forceinline__ void cp16(uint32_t dst, const void* src, int sz) {
    asm volatile("cp.async.cg.shared.global [%0], [%1], 16, %2;"
                 :: "r"(dst), "l"(src), "r"(sz) : "memory");
}
__device__ __forceinline__ void ldm_x4(uint32_t* r, uint32_t addr) {
    asm volatile("ldmatrix.sync.aligned.m8n8.x4.shared.b16 {%0,%1,%2,%3}, [%4];"
                 : "=r"(r[0]), "=r"(r[1]), "=r"(r[2]), "=r"(r[3]) : "r"(addr));
}
__device__ __forceinline__ void mma16816(float* d, const uint32_t* a, const uint32_t* b) {
    asm volatile("mma.sync.aligned.m16n8k16.row.col.f32.f16.f16.f32 "
                 "{%0,%1,%2,%3},{%4,%5,%6,%7},{%8,%9},{%0,%1,%2,%3};"
                 : "+f"(d[0]), "+f"(d[1]), "+f"(d[2]), "+f"(d[3])
                 : "r"(a[0]), "r"(a[1]), "r"(a[2]), "r"(a[3]), "r"(b[0]), "r"(b[1]));
}

// ---------------- degree / norm -------------------------------------------
__global__ void k_zero_deg() {
    int i = blockIdx.x * 256 + threadIdx.x;
    if (i < Nn) g_deg[i] = 0;
}
__global__ void k_count(const int* __restrict__ col) {
    int e = blockIdx.x * 256 + threadIdx.x;
    if (e < Ed) atomicAdd(&g_deg[col[e]], 1);
}
__global__ void k_dinv() {
    int i = blockIdx.x * 256 + threadIdx.x;
    if (i < Nn) g_dinv[i] = rsqrtf((float)(g_deg[i] + 1));  // +1 self loop
}

// ---------------- CSR build: scan + counting sort -------------------------
__global__ void k_scan1() {
    __shared__ int sh[256];
    int b = blockIdx.x, t = threadIdx.x;
    int i = b * 256 + t;
    int v = (i < Nn) ? g_deg[i] : 0;
    sh[t] = v;
    __syncthreads();
    int acc = v;
#pragma unroll
    for (int d = 1; d < 256; d <<= 1) {
        int u = (t >= d) ? sh[t - d] : 0;
        __syncthreads();
        acc += u;
        sh[t] = acc;
        __syncthreads();
    }
    if (i < Nn) g_off[i] = acc - v;
    if (t == 255) g_bsum[b] = acc;
}
__global__ void k_scan2() {
    __shared__ int sh[512];
    int t = threadIdx.x;
    int v = (t < NB_SCAN) ? g_bsum[t] : 0;
    sh[t] = v;
    __syncthreads();
    int acc = v;
#pragma unroll
    for (int d = 1; d < 512; d <<= 1) {
        int u = (t >= d) ? sh[t - d] : 0;
        __syncthreads();
        acc += u;
        sh[t] = acc;
        __syncthreads();
    }
    if (t < NB_SCAN) g_bsum[t] = acc - v;
}
__global__ void k_scan3() {
    int i = blockIdx.x * 256 + threadIdx.x;
    if (i >= Nn) return;
    int o = g_off[i] + g_bsum[i >> 8];
    g_off[i] = o;
    g_cursor[i] = o;
}
__global__ void k_build(const int* __restrict__ rowi, const int* __restrict__ coli) {
    int e = blockIdx.x * 256 + threadIdx.x;
    if (e >= Ed) return;
    int pos = atomicAdd(&g_cursor[coli[e]], 1);
    g_esrc[pos] = rowi[e];
}

// ---------------- convert x -> hcat fp16 [:, 0:512] -----------------------
__global__ void k_convx(const float* __restrict__ x) {
    int idx = blockIdx.x * 256 + threadIdx.x;     // Nn*128 float4s
    if (idx >= Nn * 128) return;
    int n = idx >> 7, q = idx & 127;
    float4 v = ((const float4*)x)[(size_t)n * 128 + q];
    __half h[4];
    h[0] = __float2half(v.x); h[1] = __float2half(v.y);
    h[2] = __float2half(v.z); h[3] = __float2half(v.w);
    *(uint2*)(g_hcat + (size_t)n * HC + q * 4) = *(const uint2*)h;
}

// ---------------- convert ALL weights upfront (fp16) ----------------------
__global__ void k_convW_all(const float* __restrict__ W0, const float* __restrict__ W1,
                            const float* __restrict__ W2, const float* __restrict__ W3,
                            const float* __restrict__ W4, const float* __restrict__ W5,
                            const float* __restrict__ Wlin) {
    const int base[8] = {0, 32768, 69632, 110592, 155648, 204800, 258048, 315392};
    const float* Ws[7] = {W0, W1, W2, W3, W4, W5, Wlin};
    int idx = blockIdx.x * 256 + threadIdx.x;
    if (idx >= 315392) return;
    int l = 0;
#pragma unroll
    for (int j = 1; j < 7; j++) if (idx >= base[j]) l = j;
    int e = idx - base[l];
    int k = e >> 6, n = e & 63;
    float w;
    if (l < 6) w = Ws[l][k * 64 + n];
    else       w = (n < Cdim) ? Ws[6][k * Cdim + n] : 0.f;
    g_WtA[(size_t)l * WSLOT + (size_t)n * HC + k] = __float2half(w);
}

// ---------------- mma.sync GEMM: g_lin[N,64] = hcat[:, :K] @ W ------------
// CTA: 128 rows x 64 cols, 256 threads / 8 warps (each warp 16x64).
// A, B single fp16 (1 product). K-chunks of 64, double-buffered, SW128.
// Stage: A [0,16K) B [16K,24K).
// mode 0: write g_lin.  mode 1: fused +blin, log_softmax, write out[N,40].
#define STAGE_BYTES 24576
__global__ void __launch_bounds__(256, 4) k_gemm_mma(int K, int wslot, int mode,
                                                     const float* __restrict__ blin,
                                                     float* __restrict__ out) {
    extern __shared__ char smem[];
    uint32_t sbase = smem_u32(smem);
    uint32_t data = (sbase + 1023) & ~1023u;

    int t = threadIdx.x, wid = t >> 5, lane = t & 31;
    int rowBase = blockIdx.x * 128;
    int m0 = wid * 16;
    const __half* Wt = g_WtA + (size_t)wslot * WSLOT;

    float acc[8][4];
#pragma unroll
    for (int j = 0; j < 8; j++)
#pragma unroll
        for (int k = 0; k < 4; k++) acc[j][k] = 0.f;

    auto load_chunk = [&](int c, int s) {
        uint32_t sa = data + s * STAGE_BYTES;
        // A: 128 rows x 64 k (128B/row) = 1024 cp16, 4 per thread
#pragma unroll
        for (int i = 0; i < 4; i++) {
            int idx = t + i * 256;           // 0..1023
            int r = idx >> 3, g = idx & 7;
            int gr = rowBase + r;
            int sz = (gr < Nn) ? 16 : 0;
            int grc = (gr < Nn) ? gr : (Nn - 1);
            size_t go = (size_t)grc * HC + c * 64 + g * 8;
            cp16(sa + swz(r * 128 + g * 16), g_hcat + go, sz);
        }
        // B: 64 n-rows x 64 k = 512 cp16, 2 per thread
#pragma unroll
        for (int i = 0; i < 2; i++) {
            int idx = t + i * 256;           // 0..511
            int n = idx >> 3, g = idx & 7;
            size_t go = (size_t)n * HC + c * 64 + g * 8;
            cp16(sa + 16384 + swz(n * 128 + g * 16), Wt + go, 16);
        }
        asm volatile("cp.async.commit_group;" ::: "memory");
    };

    int nC = K / 64;
    load_chunk(0, 0);
    load_chunk(1, 1);

    for (int c = 0; c < nC; c++) {
        int s = c & 1;
        if (c + 1 < nC) asm volatile("cp.async.wait_group 1;" ::: "memory");
        else            asm volatile("cp.async.wait_group 0;" ::: "memory");
        __syncthreads();

        uint32_t sa = data + s * STAGE_BYTES;
#pragma unroll
        for (int ks = 0; ks < 4; ks++) {
            // A fragment: 1 m-tile (16x16)
            uint32_t a[4];
            {
                int row = m0 + (lane & 15);
                uint32_t off = swz(row * 128 + ks * 32 + (lane >> 4) * 16);
                ldm_x4(a, sa + off);
            }
            // B fragments: x4 loads 2 n-tiles at once
            uint32_t bf[8][2];
#pragma unroll
            for (int j2 = 0; j2 < 4; j2++) {
                int nr = j2 * 16 + ((lane >> 4) * 8) + (lane & 7);
                int kh = (lane >> 3) & 1;
                uint32_t off = swz(nr * 128 + ks * 32 + kh * 16);
                uint32_t tmp[4];
                ldm_x4(tmp, sa + 16384 + off);
                bf[2 * j2][0] = tmp[0]; bf[2 * j2][1] = tmp[1];
                bf[2 * j2 + 1][0] = tmp[2]; bf[2 * j2 + 1][1] = tmp[3];
            }
#pragma unroll
            for (int j = 0; j < 8; j++)
                mma16816(acc[j], a, bf[j]);
        }
        __syncthreads();
        if (c + 2 < nC) load_chunk(c + 2, s);
    }

    int rBase = rowBase + m0 + (lane >> 2);
    int cBase = (lane & 3) * 2;

    if (mode == 0) {
#pragma unroll
        for (int j = 0; j < 8; j++) {
            int col = j * 8 + cBase;
            if (rBase < Nn)
                *(float2*)(g_lin + (size_t)rBase * 64 + col) = make_float2(acc[j][0], acc[j][1]);
            if (rBase + 8 < Nn)
                *(float2*)(g_lin + (size_t)(rBase + 8) * 64 + col) = make_float2(acc[j][2], acc[j][3]);
        }
    } else {
        // fused bias + log_softmax over valid cols 0..39 (j = 0..4 per thread).
        float v0[10], v1[10];
        float mx0 = -3.0e38f, mx1 = -3.0e38f;
#pragma unroll
        for (int j = 0; j < 5; j++) {
            int col = j * 8 + cBase;
            float b0 = __ldg(&blin[col]), b1 = __ldg(&blin[col + 1]);
            v0[2 * j]     = acc[j][0] + b0;
            v0[2 * j + 1] = acc[j][1] + b1;
            v1[2 * j]     = acc[j][2] + b0;
            v1[2 * j + 1] = acc[j][3] + b1;
            mx0 = fmaxf(mx0, fmaxf(v0[2 * j], v0[2 * j + 1]));
            mx1 = fmaxf(mx1, fmaxf(v1[2 * j], v1[2 * j + 1]));
        }
        mx0 = fmaxf(mx0, __shfl_xor_sync(0xffffffffu, mx0, 1));
        mx0 = fmaxf(mx0, __shfl_xor_sync(0xffffffffu, mx0, 2));
        mx1 = fmaxf(mx1, __shfl_xor_sync(0xffffffffu, mx1, 1));
        mx1 = fmaxf(mx1, __shfl_xor_sync(0xffffffffu, mx1, 2));
        float s0 = 0.f, s1 = 0.f;
#pragma unroll
        for (int j = 0; j < 10; j++) {
            s0 += expf(v0[j] - mx0);
            s1 += expf(v1[j] - mx1);
        }
        s0 += __shfl_xor_sync(0xffffffffu, s0, 1);
        s0 += __shfl_xor_sync(0xffffffffu, s0, 2);
        s1 += __shfl_xor_sync(0xffffffffu, s1, 1);
        s1 += __shfl_xor_sync(0xffffffffu, s1, 2);
        float lg0 = mx0 + logf(s0), lg1 = mx1 + logf(s1);
#pragma unroll
        for (int j = 0; j < 5; j++) {
            int col = j * 8 + cBase;
            if (rBase < Nn)
                *(float2*)(out + (size_t)rBase * Cdim + col) =
                    make_float2(v0[2 * j] - lg0, v0[2 * j + 1] - lg0);
            if (rBase + 8 < Nn)
                *(float2*)(out + (size_t)(rBase + 8) * Cdim + col) =
                    make_float2(v1[2 * j] - lg1, v1[2 * j + 1] - lg1);
        }
    }
}

// ---------------- fused CSR aggregate + self-loop + bias + relu -> fp16 ----
// 16 threads per node; thread q handles float4 q (fully coalesced rows).
__global__ void k_agg_fused(const float* __restrict__ bias, int off) {
    int gid = blockIdx.x * 256 + threadIdx.x;
    int c = gid >> 4;
    if (c >= Nn) return;
    int q = gid & 15;

    int e0 = g_off[c];
    int d  = g_deg[c];
    float4 a = make_float4(0.f, 0.f, 0.f, 0.f);
    for (int i = 0; i < d; i++) {
        int r = __ldg(&g_esrc[e0 + i]);
        float w = __ldg(&g_dinv[r]);
        float4 v = __ldg(((const float4*)(g_lin + (size_t)r * 64)) + q);
        a.x += w * v.x; a.y += w * v.y; a.z += w * v.z; a.w += w * v.w;
    }
    float dc = g_dinv[c];
    float dc2 = dc * dc;
    float4 s0 = __ldg(((const float4*)(g_lin + (size_t)c * 64)) + q);
    float4 b0 = ((const float4*)bias)[q];

    __half h[4];
    h[0] = __float2half(fmaxf(dc * a.x + dc2 * s0.x + b0.x, 0.f));
    h[1] = __float2half(fmaxf(dc * a.y + dc2 * s0.y + b0.y, 0.f));
    h[2] = __float2half(fmaxf(dc * a.z + dc2 * s0.z + b0.z, 0.f));
    h[3] = __float2half(fmaxf(dc * a.w + dc2 * s0.w + b0.w, 0.f));
    *(uint2*)(g_hcat + (size_t)c * HC + off + q * 4) = *(const uint2*)h;
}

// ---------------- launch ---------------------------------------------------
static inline int nb(int n, int b) { return (n + b - 1) / b; }
#define GEMM_SMEM (2 * STAGE_BYTES + 1024)

extern "C" void kernel_launch(void* const* d_in, const int* in_sizes, int n_in,
                              void* d_out, int out_size) {
    const float* x    = (const float*)d_in[0];
    const int*   ei   = (const int*)d_in[1];
    const int*   rowi = ei;          // edge_index[0] = source
    const int*   coli = ei + Ed;     // edge_index[1] = target
    const float* W[6];
    const float* b[6];
    for (int i = 0; i < 6; i++) {
        W[i] = (const float*)d_in[2 + 2 * i];
        b[i] = (const float*)d_in[3 + 2 * i];
    }
    const float* Wlin = (const float*)d_in[14];
    const float* blin = (const float*)d_in[15];
    float* out = (float*)d_out;

    cudaFuncSetAttribute(k_gemm_mma, cudaFuncAttributeMaxDynamicSharedMemorySize, GEMM_SMEM);

    k_zero_deg<<<nb(Nn, 256), 256>>>();
    k_count<<<nb(Ed, 256), 256>>>(coli);
    k_dinv<<<nb(Nn, 256), 256>>>();
    k_scan1<<<NB_SCAN, 256>>>();
    k_scan2<<<1, 512>>>();
    k_scan3<<<nb(Nn, 256), 256>>>();
    k_build<<<nb(Ed, 256), 256>>>(rowi, coli);
    k_convx<<<nb(Nn * 128, 256), 256>>>(x);
    k_convW_all<<<nb(315392, 256), 256>>>(W[0], W[1], W[2], W[3], W[4], W[5], Wlin);

    int gemm_grid = nb(Nn, 128);
    for (int i = 0; i < 6; i++) {
        int K   = Fdim + Hdim * i;        // 512,576,...,832
        int off = K;
        k_gemm_mma<<<gemm_grid, 256, GEMM_SMEM>>>(K, i, 0, nullptr, nullptr);
        k_agg_fused<<<nb(Nn * 16, 256), 256>>>(b[i], off);
    }

    k_gemm_mma<<<gemm_grid, 256, GEMM_SMEM>>>(HC, 6, 1, blin, out);
}

// round 13
// speedup vs baseline: 1.6192x; 1.0186x over previous
#include <cuda_runtime.h>
#include <cuda_fp16.h>
#include <cstdint>

#define Nn   100000
#define Fdim 512
#define Hdim 64
#define Cdim 40
#define Ed   1600000
#define HC   896      // F + 6*H  (hcat width)
#define NB_SCAN 391   // ceil(Nn/256)
#define WSLOT (64 * HC)

// ---------------- scratch (device globals; no allocation allowed) ----------
__device__ __half g_hcat[(size_t)Nn * HC];            // 179 MB, fp16
__device__ __half g_lin[(size_t)Nn * Hdim];           // GEMM output (64 cols, fp16)
__device__ float g_dinv[Nn];
__device__ int   g_deg[Nn];
__device__ int   g_off[Nn];                           // CSR offsets
__device__ int   g_cursor[Nn];
__device__ int   g_bsum[NB_SCAN];
__device__ int   g_esrc[Ed];                          // CSR: source node per edge slot
__device__ __half g_WtA[7 * WSLOT];                   // weights transposed [n][k], fp16

// ---------------- tiny PTX helpers ----------------------------------------
__device__ __forceinline__ uint32_t smem_u32(const void* p) {
    uint32_t a;
    asm("{ .reg .u64 t; cvta.to.shared.u64 t, %1; cvt.u32.u64 %0, t; }" : "=r"(a) : "l"(p));
    return a;
}
__device__ __forceinline__ uint32_t swz(uint32_t off) { return off ^ ((off >> 3) & 0x70); }

__device__ __forceinline__ void cp16(uint32_t dst, const void* src, int sz) {
    asm volatile("cp.async.cg.shared.global [%0], [%1], 16, %2;"
                 :: "r"(dst), "l"(src), "r"(sz) : "memory");
}
__device__ __forceinline__ void ldm_x4(uint32_t* r, uint32_t addr) {
    asm volatile("ldmatrix.sync.aligned.m8n8.x4.shared.b16 {%0,%1,%2,%3}, [%4];"
                 : "=r"(r[0]), "=r"(r[1]), "=r"(r[2]), "=r"(r[3]) : "r"(addr));
}
__device__ __forceinline__ void mma16816(float* d, const uint32_t* a, const uint32_t* b) {
    asm volatile("mma.sync.aligned.m16n8k16.row.col.f32.f16.f16.f32 "
                 "{%0,%1,%2,%3},{%4,%5,%6,%7},{%8,%9},{%0,%1,%2,%3};"
                 : "+f"(d[0]), "+f"(d[1]), "+f"(d[2]), "+f"(d[3])
                 : "r"(a[0]), "r"(a[1]), "r"(a[2]), "r"(a[3]), "r"(b[0]), "r"(b[1]));
}

// ---------------- degree / norm -------------------------------------------
__global__ void k_zero_deg() {
    int i = blockIdx.x * 256 + threadIdx.x;
    if (i < Nn) g_deg[i] = 0;
}
__global__ void k_count(const int* __restrict__ col) {
    int e = blockIdx.x * 256 + threadIdx.x;
    if (e < Ed) atomicAdd(&g_deg[col[e]], 1);
}
__global__ void k_dinv() {
    int i = blockIdx.x * 256 + threadIdx.x;
    if (i < Nn) g_dinv[i] = rsqrtf((float)(g_deg[i] + 1));  // +1 self loop
}

// ---------------- CSR build: scan + counting sort -------------------------
__global__ void k_scan1() {
    __shared__ int sh[256];
    int b = blockIdx.x, t = threadIdx.x;
    int i = b * 256 + t;
    int v = (i < Nn) ? g_deg[i] : 0;
    sh[t] = v;
    __syncthreads();
    int acc = v;
#pragma unroll
    for (int d = 1; d < 256; d <<= 1) {
        int u = (t >= d) ? sh[t - d] : 0;
        __syncthreads();
        acc += u;
        sh[t] = acc;
        __syncthreads();
    }
    if (i < Nn) g_off[i] = acc - v;
    if (t == 255) g_bsum[b] = acc;
}
__global__ void k_scan2() {
    __shared__ int sh[512];
    int t = threadIdx.x;
    int v = (t < NB_SCAN) ? g_bsum[t] : 0;
    sh[t] = v;
    __syncthreads();
    int acc = v;
#pragma unroll
    for (int d = 1; d < 512; d <<= 1) {
        int u = (t >= d) ? sh[t - d] : 0;
        __syncthreads();
        acc += u;
        sh[t] = acc;
        __syncthreads();
    }
    if (t < NB_SCAN) g_bsum[t] = acc - v;
}
__global__ void k_scan3() {
    int i = blockIdx.x * 256 + threadIdx.x;
    if (i >= Nn) return;
    int o = g_off[i] + g_bsum[i >> 8];
    g_off[i] = o;
    g_cursor[i] = o;
}
__global__ void k_build(const int* __restrict__ rowi, const int* __restrict__ coli) {
    int e = blockIdx.x * 256 + threadIdx.x;
    if (e >= Ed) return;
    int pos = atomicAdd(&g_cursor[coli[e]], 1);
    g_esrc[pos] = rowi[e];
}

// ---------------- convert x -> hcat fp16 [:, 0:512] -----------------------
__global__ void k_convx(const float* __restrict__ x) {
    int idx = blockIdx.x * 256 + threadIdx.x;     // Nn*128 float4s
    if (idx >= Nn * 128) return;
    int n = idx >> 7, q = idx & 127;
    float4 v = ((const float4*)x)[(size_t)n * 128 + q];
    __half h[4];
    h[0] = __float2half(v.x); h[1] = __float2half(v.y);
    h[2] = __float2half(v.z); h[3] = __float2half(v.w);
    *(uint2*)(g_hcat + (size_t)n * HC + q * 4) = *(const uint2*)h;
}

// ---------------- convert ALL weights upfront (fp16) ----------------------
__global__ void k_convW_all(const float* __restrict__ W0, const float* __restrict__ W1,
                            const float* __restrict__ W2, const float* __restrict__ W3,
                            const float* __restrict__ W4, const float* __restrict__ W5,
                            const float* __restrict__ Wlin) {
    const int base[8] = {0, 32768, 69632, 110592, 155648, 204800, 258048, 315392};
    const float* Ws[7] = {W0, W1, W2, W3, W4, W5, Wlin};
    int idx = blockIdx.x * 256 + threadIdx.x;
    if (idx >= 315392) return;
    int l = 0;
#pragma unroll
    for (int j = 1; j < 7; j++) if (idx >= base[j]) l = j;
    int e = idx - base[l];
    int k = e >> 6, n = e & 63;
    float w;
    if (l < 6) w = Ws[l][k * 64 + n];
    else       w = (n < Cdim) ? Ws[6][k * Cdim + n] : 0.f;
    g_WtA[(size_t)l * WSLOT + (size_t)n * HC + k] = __float2half(w);
}

// ---------------- mma.sync GEMM: g_lin[N,64] = hcat[:, :K] @ W ------------
// CTA: 128 rows x 64 cols, 256 threads / 8 warps (each warp 16x64).
// A, B single fp16 (1 product). K-chunks of 64, double-buffered, SW128.
// Stage: A [0,16K) B [16K,24K).
// mode 0: write g_lin fp16.  mode 1: fused +blin, log_softmax, out[N,40] f32.
#define STAGE_BYTES 24576
__global__ void __launch_bounds__(256, 4) k_gemm_mma(int K, int wslot, int mode,
                                                     const float* __restrict__ blin,
                                                     float* __restrict__ out) {
    extern __shared__ char smem[];
    uint32_t sbase = smem_u32(smem);
    uint32_t data = (sbase + 1023) & ~1023u;

    int t = threadIdx.x, wid = t >> 5, lane = t & 31;
    int rowBase = blockIdx.x * 128;
    int m0 = wid * 16;
    const __half* Wt = g_WtA + (size_t)wslot * WSLOT;

    float acc[8][4];
#pragma unroll
    for (int j = 0; j < 8; j++)
#pragma unroll
        for (int k = 0; k < 4; k++) acc[j][k] = 0.f;

    auto load_chunk = [&](int c, int s) {
        uint32_t sa = data + s * STAGE_BYTES;
#pragma unroll
        for (int i = 0; i < 4; i++) {
            int idx = t + i * 256;           // 0..1023
            int r = idx >> 3, g = idx & 7;
            int gr = rowBase + r;
            int sz = (gr < Nn) ? 16 : 0;
            int grc = (gr < Nn) ? gr : (Nn - 1);
            size_t go = (size_t)grc * HC + c * 64 + g * 8;
            cp16(sa + swz(r * 128 + g * 16), g_hcat + go, sz);
        }
#pragma unroll
        for (int i = 0; i < 2; i++) {
            int idx = t + i * 256;           // 0..511
            int n = idx >> 3, g = idx & 7;
            size_t go = (size_t)n * HC + c * 64 + g * 8;
            cp16(sa + 16384 + swz(n * 128 + g * 16), Wt + go, 16);
        }
        asm volatile("cp.async.commit_group;" ::: "memory");
    };

    int nC = K / 64;
    load_chunk(0, 0);
    load_chunk(1, 1);

    for (int c = 0; c < nC; c++) {
        int s = c & 1;
        if (c + 1 < nC) asm volatile("cp.async.wait_group 1;" ::: "memory");
        else            asm volatile("cp.async.wait_group 0;" ::: "memory");
        __syncthreads();

        uint32_t sa = data + s * STAGE_BYTES;
#pragma unroll
        for (int ks = 0; ks < 4; ks++) {
            uint32_t a[4];
            {
                int row = m0 + (lane & 15);
                uint32_t off = swz(row * 128 + ks * 32 + (lane >> 4) * 16);
                ldm_x4(a, sa + off);
            }
            uint32_t bf[8][2];
#pragma unroll
            for (int j2 = 0; j2 < 4; j2++) {
                int nr = j2 * 16 + ((lane >> 4) * 8) + (lane & 7);
                int kh = (lane >> 3) & 1;
                uint32_t off = swz(nr * 128 + ks * 32 + kh * 16);
                uint32_t tmp[4];
                ldm_x4(tmp, sa + 16384 + off);
                bf[2 * j2][0] = tmp[0]; bf[2 * j2][1] = tmp[1];
                bf[2 * j2 + 1][0] = tmp[2]; bf[2 * j2 + 1][1] = tmp[3];
            }
#pragma unroll
            for (int j = 0; j < 8; j++)
                mma16816(acc[j], a, bf[j]);
        }
        __syncthreads();
        if (c + 2 < nC) load_chunk(c + 2, s);
    }

    int rBase = rowBase + m0 + (lane >> 2);
    int cBase = (lane & 3) * 2;

    if (mode == 0) {
#pragma unroll
        for (int j = 0; j < 8; j++) {
            int col = j * 8 + cBase;
            if (rBase < Nn) {
                __half2 h = __floats2half2_rn(acc[j][0], acc[j][1]);
                *(uint32_t*)(g_lin + (size_t)rBase * 64 + col) = *(const uint32_t*)&h;
            }
            if (rBase + 8 < Nn) {
                __half2 h = __floats2half2_rn(acc[j][2], acc[j][3]);
                *(uint32_t*)(g_lin + (size_t)(rBase + 8) * 64 + col) = *(const uint32_t*)&h;
            }
        }
    } else {
        // fused bias + log_softmax over valid cols 0..39 (j = 0..4 per thread).
        float v0[10], v1[10];
        float mx0 = -3.0e38f, mx1 = -3.0e38f;
#pragma unroll
        for (int j = 0; j < 5; j++) {
            int col = j * 8 + cBase;
            float b0 = __ldg(&blin[col]), b1 = __ldg(&blin[col + 1]);
            v0[2 * j]     = acc[j][0] + b0;
            v0[2 * j + 1] = acc[j][1] + b1;
            v1[2 * j]     = acc[j][2] + b0;
            v1[2 * j + 1] = acc[j][3] + b1;
            mx0 = fmaxf(mx0, fmaxf(v0[2 * j], v0[2 * j + 1]));
            mx1 = fmaxf(mx1, fmaxf(v1[2 * j], v1[2 * j + 1]));
        }
        mx0 = fmaxf(mx0, __shfl_xor_sync(0xffffffffu, mx0, 1));
        mx0 = fmaxf(mx0, __shfl_xor_sync(0xffffffffu, mx0, 2));
        mx1 = fmaxf(mx1, __shfl_xor_sync(0xffffffffu, mx1, 1));
        mx1 = fmaxf(mx1, __shfl_xor_sync(0xffffffffu, mx1, 2));
        float s0 = 0.f, s1 = 0.f;
#pragma unroll
        for (int j = 0; j < 10; j++) {
            s0 += expf(v0[j] - mx0);
            s1 += expf(v1[j] - mx1);
        }
        s0 += __shfl_xor_sync(0xffffffffu, s0, 1);
        s0 += __shfl_xor_sync(0xffffffffu, s0, 2);
        s1 += __shfl_xor_sync(0xffffffffu, s1, 1);
        s1 += __shfl_xor_sync(0xffffffffu, s1, 2);
        float lg0 = mx0 + logf(s0), lg1 = mx1 + logf(s1);
#pragma unroll
        for (int j = 0; j < 5; j++) {
            int col = j * 8 + cBase;
            if (rBase < Nn)
                *(float2*)(out + (size_t)rBase * Cdim + col) =
                    make_float2(v0[2 * j] - lg0, v0[2 * j + 1] - lg0);
            if (rBase + 8 < Nn)
                *(float2*)(out + (size_t)(rBase + 8) * Cdim + col) =
                    make_float2(v1[2 * j] - lg1, v1[2 * j + 1] - lg1);
        }
    }
}

// ---------------- fused CSR aggregate + self-loop + bias + relu -> fp16 ----
// 16 threads per node; thread q handles halves q*4..q*4+3 (8B, coalesced).
__global__ void k_agg_fused(const float* __restrict__ bias, int off) {
    int gid = blockIdx.x * 256 + threadIdx.x;
    int c = gid >> 4;
    if (c >= Nn) return;
    int q = gid & 15;

    int e0 = g_off[c];
    int d  = g_deg[c];
    float ax = 0.f, ay = 0.f, az = 0.f, aw = 0.f;
    for (int i = 0; i < d; i++) {
        int r = __ldg(&g_esrc[e0 + i]);
        float w = __ldg(&g_dinv[r]);
        uint2 raw = __ldg((const uint2*)(g_lin + (size_t)r * 64 + q * 4));
        float2 p0 = __half22float2(*(const __half2*)&raw.x);
        float2 p1 = __half22float2(*(const __half2*)&raw.y);
        ax += w * p0.x; ay += w * p0.y; az += w * p1.x; aw += w * p1.y;
    }
    float dc = g_dinv[c];
    float dc2 = dc * dc;
    uint2 sraw = __ldg((const uint2*)(g_lin + (size_t)c * 64 + q * 4));
    float2 sp0 = __half22float2(*(const __half2*)&sraw.x);
    float2 sp1 = __half22float2(*(const __half2*)&sraw.y);
    float4 b0 = ((const float4*)bias)[q];

    __half h[4];
    h[0] = __float2half(fmaxf(dc * ax + dc2 * sp0.x + b0.x, 0.f));
    h[1] = __float2half(fmaxf(dc * ay + dc2 * sp0.y + b0.y, 0.f));
    h[2] = __float2half(fmaxf(dc * az + dc2 * sp1.x + b0.z, 0.f));
    h[3] = __float2half(fmaxf(dc * aw + dc2 * sp1.y + b0.w, 0.f));
    *(uint2*)(g_hcat + (size_t)c * HC + off + q * 4) = *(const uint2*)h;
}

// ---------------- launch ---------------------------------------------------
static inline int nb(int n, int b) { return (n + b - 1) / b; }
#define GEMM_SMEM (2 * STAGE_BYTES + 1024)

extern "C" void kernel_launch(void* const* d_in, const int* in_sizes, int n_in,
                              void* d_out, int out_size) {
    const float* x    = (const float*)d_in[0];
    const int*   ei   = (const int*)d_in[1];
    const int*   rowi = ei;          // edge_index[0] = source
    const int*   coli = ei + Ed;     // edge_index[1] = target
    const float* W[6];
    const float* b[6];
    for (int i = 0; i < 6; i++) {
        W[i] = (const float*)d_in[2 + 2 * i];
        b[i] = (const float*)d_in[3 + 2 * i];
    }
    const float* Wlin = (const float*)d_in[14];
    const float* blin = (const float*)d_in[15];
    float* out = (float*)d_out;

    cudaFuncSetAttribute(k_gemm_mma, cudaFuncAttributeMaxDynamicSharedMemorySize, GEMM_SMEM);

    k_zero_deg<<<nb(Nn, 256), 256>>>();
    k_count<<<nb(Ed, 256), 256>>>(coli);
    k_dinv<<<nb(Nn, 256), 256>>>();
    k_scan1<<<NB_SCAN, 256>>>();
    k_scan2<<<1, 512>>>();
    k_scan3<<<nb(Nn, 256), 256>>>();
    k_build<<<nb(Ed, 256), 256>>>(rowi, coli);
    k_convx<<<nb(Nn * 128, 256), 256>>>(x);
    k_convW_all<<<nb(315392, 256), 256>>>(W[0], W[1], W[2], W[3], W[4], W[5], Wlin);

    int gemm_grid = nb(Nn, 128);
    for (int i = 0; i < 6; i++) {
        int K   = Fdim + Hdim * i;        // 512,576,...,832
        int off = K;
        k_gemm_mma<<<gemm_grid, 256, GEMM_SMEM>>>(K, i, 0, nullptr, nullptr);
        k_agg_fused<<<nb(Nn * 16, 256), 256>>>(b[i], off);
    }

    k_gemm_mma<<<gemm_grid, 256, GEMM_SMEM>>>(HC, 6, 1, blin, out);
}

// round 16
// speedup vs baseline: 1.7675x; 1.0916x over previous
#include <cuda_runtime.h>
#include <cuda_fp16.h>
#include <cstdint>

#define Nn   100000
#define Fdim 512
#define Hdim 64
#define Cdim 40
#define Ed   1600000
#define HC   896      // F + 6*H  (hcat width)
#define NB_SCAN 391   // ceil(Nn/256)
#define WSLOT (64 * HC)

// ---------------- scratch (device globals; no allocation allowed) ----------
__device__ __half g_hcat[(size_t)Nn * HC];            // 179 MB, fp16
__device__ __half g_lin[(size_t)Nn * Hdim];           // GEMM output (64 cols, fp16)
__device__ float g_dinv[Nn];
__device__ int   g_deg[Nn];
__device__ int   g_off[Nn];                           // CSR offsets
__device__ int   g_cursor[Nn];
__device__ int   g_bsum[NB_SCAN];
__device__ int   g_esrc[Ed];                          // CSR: source node per edge slot
__device__ __half g_WtA[7 * WSLOT];                   // weights transposed [n][k], fp16

// ---------------- tiny PTX helpers ----------------------------------------
__device__ __forceinline__ uint32_t smem_u32(const void* p) {
    uint32_t a;
    asm("{ .reg .u64 t; cvta.to.shared.u64 t, %1; cvt.u32.u64 %0, t; }" : "=r"(a) : "l"(p));
    return a;
}
__device__ __forceinline__ uint32_t swz(uint32_t off) { return off ^ ((off >> 3) & 0x70); }

__device__ __forceinline__ void cp16(uint32_t dst, const void* src, int sz) {
    asm volatile("cp.async.cg.shared.global [%0], [%1], 16, %2;"
                 :: "r"(dst), "l"(src), "r"(sz) : "memory");
}
__device__ __forceinline__ void ldm_x4(uint32_t* r, uint32_t addr) {
    asm volatile("ldmatrix.sync.aligned.m8n8.x4.shared.b16 {%0,%1,%2,%3}, [%4];"
                 : "=r"(r[0]), "=r"(r[1]), "=r"(r[2]), "=r"(r[3]) : "r"(addr));
}
__device__ __forceinline__ void mma16816(float* d, const uint32_t* a, const uint32_t* b) {
    asm volatile("mma.sync.aligned.m16n8k16.row.col.f32.f16.f16.f32 "
                 "{%0,%1,%2,%3},{%4,%5,%6,%7},{%8,%9},{%0,%1,%2,%3};"
                 : "+f"(d[0]), "+f"(d[1]), "+f"(d[2]), "+f"(d[3])
                 : "r"(a[0]), "r"(a[1]), "r"(a[2]), "r"(a[3]), "r"(b[0]), "r"(b[1]));
}

// ---------------- degree / norm -------------------------------------------
__global__ void k_zero_deg() {
    int i = blockIdx.x * 256 + threadIdx.x;
    if (i < Nn) g_deg[i] = 0;
}
__global__ void k_count(const int* __restrict__ col) {
    int e = blockIdx.x * 256 + threadIdx.x;
    if (e < Ed) atomicAdd(&g_deg[col[e]], 1);
}
__global__ void k_dinv() {
    int i = blockIdx.x * 256 + threadIdx.x;
    if (i < Nn) g_dinv[i] = rsqrtf((float)(g_deg[i] + 1));  // +1 self loop
}

// ---------------- CSR build: scan + counting sort -------------------------
__global__ void k_scan1() {
    __shared__ int sh[256];
    int b = blockIdx.x, t = threadIdx.x;
    int i = b * 256 + t;
    int v = (i < Nn) ? g_deg[i] : 0;
    sh[t] = v;
    __syncthreads();
    int acc = v;
#pragma unroll
    for (int d = 1; d < 256; d <<= 1) {
        int u = (t >= d) ? sh[t - d] : 0;
        __syncthreads();
        acc += u;
        sh[t] = acc;
        __syncthreads();
    }
    if (i < Nn) g_off[i] = acc - v;
    if (t == 255) g_bsum[b] = acc;
}
__global__ void k_scan2() {
    __shared__ int sh[512];
    int t = threadIdx.x;
    int v = (t < NB_SCAN) ? g_bsum[t] : 0;
    sh[t] = v;
    __syncthreads();
    int acc = v;
#pragma unroll
    for (int d = 1; d < 512; d <<= 1) {
        int u = (t >= d) ? sh[t - d] : 0;
        __syncthreads();
        acc += u;
        sh[t] = acc;
        __syncthreads();
    }
    if (t < NB_SCAN) g_bsum[t] = acc - v;
}
__global__ void k_scan3() {
    int i = blockIdx.x * 256 + threadIdx.x;
    if (i >= Nn) return;
    int o = g_off[i] + g_bsum[i >> 8];
    g_off[i] = o;
    g_cursor[i] = o;
}
__global__ void k_build(const int* __restrict__ rowi, const int* __restrict__ coli) {
    int e = blockIdx.x * 256 + threadIdx.x;
    if (e >= Ed) return;
    int pos = atomicAdd(&g_cursor[coli[e]], 1);
    g_esrc[pos] = rowi[e];
}

// ---------------- convert x -> hcat fp16 [:, 0:512] -----------------------
__global__ void k_convx(const float* __restrict__ x) {
    int idx = blockIdx.x * 256 + threadIdx.x;     // Nn*128 float4s
    if (idx >= Nn * 128) return;
    int n = idx >> 7, q = idx & 127;
    float4 v = ((const float4*)x)[(size_t)n * 128 + q];
    __half h[4];
    h[0] = __float2half(v.x); h[1] = __float2half(v.y);
    h[2] = __float2half(v.z); h[3] = __float2half(v.w);
    *(uint2*)(g_hcat + (size_t)n * HC + q * 4) = *(const uint2*)h;
}

// ---------------- convert ALL weights upfront (fp16) ----------------------
__global__ void k_convW_all(const float* __restrict__ W0, const float* __restrict__ W1,
                            const float* __restrict__ W2, const float* __restrict__ W3,
                            const float* __restrict__ W4, const float* __restrict__ W5,
                            const float* __restrict__ Wlin) {
    const int base[8] = {0, 32768, 69632, 110592, 155648, 204800, 258048, 315392};
    const float* Ws[7] = {W0, W1, W2, W3, W4, W5, Wlin};
    int idx = blockIdx.x * 256 + threadIdx.x;
    if (idx >= 315392) return;
    int l = 0;
#pragma unroll
    for (int j = 1; j < 7; j++) if (idx >= base[j]) l = j;
    int e = idx - base[l];
    int k = e >> 6, n = e & 63;
    float w;
    if (l < 6) w = Ws[l][k * 64 + n];
    else       w = (n < Cdim) ? Ws[6][k * Cdim + n] : 0.f;
    g_WtA[(size_t)l * WSLOT + (size_t)n * HC + k] = __float2half(w);
}

// ---------------- mma.sync GEMM: g_lin[N,64] = hcat[:, :K] @ W ------------
// CTA: 128 rows x 64 cols, 256 threads / 8 warps (each warp 16x64).
// A, B single fp16 (1 product). K-chunks of 64, double-buffered, SW128.
// Stage: A [0,16K) B [16K,24K).
// mode 0: write g_lin fp16.  mode 1: fused +blin, log_softmax, out[N,40] f32.
#define STAGE_BYTES 24576
__global__ void __launch_bounds__(256, 4) k_gemm_mma(int K, int wslot, int mode,
                                                     const float* __restrict__ blin,
                                                     float* __restrict__ out) {
    extern __shared__ char smem[];
    uint32_t sbase = smem_u32(smem);
    uint32_t data = (sbase + 1023) & ~1023u;

    int t = threadIdx.x, wid = t >> 5, lane = t & 31;
    int rowBase = blockIdx.x * 128;
    int m0 = wid * 16;
    const __half* Wt = g_WtA + (size_t)wslot * WSLOT;

    float acc[8][4];
#pragma unroll
    for (int j = 0; j < 8; j++)
#pragma unroll
        for (int k = 0; k < 4; k++) acc[j][k] = 0.f;

    auto load_chunk = [&](int c, int s) {
        uint32_t sa = data + s * STAGE_BYTES;
#pragma unroll
        for (int i = 0; i < 4; i++) {
            int idx = t + i * 256;           // 0..1023
            int r = idx >> 3, g = idx & 7;
            int gr = rowBase + r;
            int sz = (gr < Nn) ? 16 : 0;
            int grc = (gr < Nn) ? gr : (Nn - 1);
            size_t go = (size_t)grc * HC + c * 64 + g * 8;
            cp16(sa + swz(r * 128 + g * 16), g_hcat + go, sz);
        }
#pragma unroll
        for (int i = 0; i < 2; i++) {
            int idx = t + i * 256;           // 0..511
            int n = idx >> 3, g = idx & 7;
            size_t go = (size_t)n * HC + c * 64 + g * 8;
            cp16(sa + 16384 + swz(n * 128 + g * 16), Wt + go, 16);
        }
        asm volatile("cp.async.commit_group;" ::: "memory");
    };

    int nC = K / 64;
    load_chunk(0, 0);
    load_chunk(1, 1);

    for (int c = 0; c < nC; c++) {
        int s = c & 1;
        if (c + 1 < nC) asm volatile("cp.async.wait_group 1;" ::: "memory");
        else            asm volatile("cp.async.wait_group 0;" ::: "memory");
        __syncthreads();

        uint32_t sa = data + s * STAGE_BYTES;
#pragma unroll
        for (int ks = 0; ks < 4; ks++) {
            uint32_t a[4];
            {
                int row = m0 + (lane & 15);
                uint32_t off = swz(row * 128 + ks * 32 + (lane >> 4) * 16);
                ldm_x4(a, sa + off);
            }
            uint32_t bf[8][2];
#pragma unroll
            for (int j2 = 0; j2 < 4; j2++) {
                int nr = j2 * 16 + ((lane >> 4) * 8) + (lane & 7);
                int kh = (lane >> 3) & 1;
                uint32_t off = swz(nr * 128 + ks * 32 + kh * 16);
                uint32_t tmp[4];
                ldm_x4(tmp, sa + 16384 + off);
                bf[2 * j2][0] = tmp[0]; bf[2 * j2][1] = tmp[1];
                bf[2 * j2 + 1][0] = tmp[2]; bf[2 * j2 + 1][1] = tmp[3];
            }
#pragma unroll
            for (int j = 0; j < 8; j++)
                mma16816(acc[j], a, bf[j]);
        }
        __syncthreads();
        if (c + 2 < nC) load_chunk(c + 2, s);
    }

    int rBase = rowBase + m0 + (lane >> 2);
    int cBase = (lane & 3) * 2;

    if (mode == 0) {
#pragma unroll
        for (int j = 0; j < 8; j++) {
            int col = j * 8 + cBase;
            if (rBase < Nn) {
                __half2 h = __floats2half2_rn(acc[j][0], acc[j][1]);
                *(uint32_t*)(g_lin + (size_t)rBase * 64 + col) = *(const uint32_t*)&h;
            }
            if (rBase + 8 < Nn) {
                __half2 h = __floats2half2_rn(acc[j][2], acc[j][3]);
                *(uint32_t*)(g_lin + (size_t)(rBase + 8) * 64 + col) = *(const uint32_t*)&h;
            }
        }
    } else {
        // fused bias + log_softmax over valid cols 0..39 (j = 0..4 per thread).
        float v0[10], v1[10];
        float mx0 = -3.0e38f, mx1 = -3.0e38f;
#pragma unroll
        for (int j = 0; j < 5; j++) {
            int col = j * 8 + cBase;
            float b0 = __ldg(&blin[col]), b1 = __ldg(&blin[col + 1]);
            v0[2 * j]     = acc[j][0] + b0;
            v0[2 * j + 1] = acc[j][1] + b1;
            v1[2 * j]     = acc[j][2] + b0;
            v1[2 * j + 1] = acc[j][3] + b1;
            mx0 = fmaxf(mx0, fmaxf(v0[2 * j], v0[2 * j + 1]));
            mx1 = fmaxf(mx1, fmaxf(v1[2 * j], v1[2 * j + 1]));
        }
        mx0 = fmaxf(mx0, __shfl_xor_sync(0xffffffffu, mx0, 1));
        mx0 = fmaxf(mx0, __shfl_xor_sync(0xffffffffu, mx0, 2));
        mx1 = fmaxf(mx1, __shfl_xor_sync(0xffffffffu, mx1, 1));
        mx1 = fmaxf(mx1, __shfl_xor_sync(0xffffffffu, mx1, 2));
        float s0 = 0.f, s1 = 0.f;
#pragma unroll
        for (int j = 0; j < 10; j++) {
            s0 += expf(v0[j] - mx0);
            s1 += expf(v1[j] - mx1);
        }
        s0 += __shfl_xor_sync(0xffffffffu, s0, 1);
        s0 += __shfl_xor_sync(0xffffffffu, s0, 2);
        s1 += __shfl_xor_sync(0xffffffffu, s1, 1);
        s1 += __shfl_xor_sync(0xffffffffu, s1, 2);
        float lg0 = mx0 + logf(s0), lg1 = mx1 + logf(s1);
#pragma unroll
        for (int j = 0; j < 5; j++) {
            int col = j * 8 + cBase;
            if (rBase < Nn)
                *(float2*)(out + (size_t)rBase * Cdim + col) =
                    make_float2(v0[2 * j] - lg0, v0[2 * j + 1] - lg0);
            if (rBase + 8 < Nn)
                *(float2*)(out + (size_t)(rBase + 8) * Cdim + col) =
                    make_float2(v1[2 * j] - lg1, v1[2 * j + 1] - lg1);
        }
    }
}

// ---------------- fused CSR aggregate + self-loop + bias + relu -> fp16 ----
// 8 threads per node; thread q handles halves q*8..q*8+7 (16B uint4 loads).
// Edge loop unrolled x2 for MLP.
__global__ void k_agg_fused(const float* __restrict__ bias, int off) {
    int gid = blockIdx.x * 256 + threadIdx.x;
    int c = gid >> 3;
    if (c >= Nn) return;
    int q = gid & 7;

    int e0 = g_off[c];
    int d  = g_deg[c];
    float a0 = 0.f, a1 = 0.f, a2 = 0.f, a3 = 0.f;
    float a4 = 0.f, a5 = 0.f, a6 = 0.f, a7 = 0.f;

    int i = 0;
    for (; i + 2 <= d; i += 2) {
        int r0 = __ldg(&g_esrc[e0 + i]);
        int r1 = __ldg(&g_esrc[e0 + i + 1]);
        float w0 = __ldg(&g_dinv[r0]);
        float w1 = __ldg(&g_dinv[r1]);
        uint4 x0 = __ldg((const uint4*)(g_lin + (size_t)r0 * 64 + q * 8));
        uint4 x1 = __ldg((const uint4*)(g_lin + (size_t)r1 * 64 + q * 8));
        float2 p;
        p = __half22float2(*(const __half2*)&x0.x); a0 += w0 * p.x; a1 += w0 * p.y;
        p = __half22float2(*(const __half2*)&x0.y); a2 += w0 * p.x; a3 += w0 * p.y;
        p = __half22float2(*(const __half2*)&x0.z); a4 += w0 * p.x; a5 += w0 * p.y;
        p = __half22float2(*(const __half2*)&x0.w); a6 += w0 * p.x; a7 += w0 * p.y;
        p = __half22float2(*(const __half2*)&x1.x); a0 += w1 * p.x; a1 += w1 * p.y;
        p = __half22float2(*(const __half2*)&x1.y); a2 += w1 * p.x; a3 += w1 * p.y;
        p = __half22float2(*(const __half2*)&x1.z); a4 += w1 * p.x; a5 += w1 * p.y;
        p = __half22float2(*(const __half2*)&x1.w); a6 += w1 * p.x; a7 += w1 * p.y;
    }
    if (i < d) {
        int r0 = __ldg(&g_esrc[e0 + i]);
        float w0 = __ldg(&g_dinv[r0]);
        uint4 x0 = __ldg((const uint4*)(g_lin + (size_t)r0 * 64 + q * 8));
        float2 p;
        p = __half22float2(*(const __half2*)&x0.x); a0 += w0 * p.x; a1 += w0 * p.y;
        p = __half22float2(*(const __half2*)&x0.y); a2 += w0 * p.x; a3 += w0 * p.y;
        p = __half22float2(*(const __half2*)&x0.z); a4 += w0 * p.x; a5 += w0 * p.y;
        p = __half22float2(*(const __half2*)&x0.w); a6 += w0 * p.x; a7 += w0 * p.y;
    }

    float dc = g_dinv[c];
    float dc2 = dc * dc;
    uint4 sr = __ldg((const uint4*)(g_lin + (size_t)c * 64 + q * 8));
    float4 b0 = ((const float4*)bias)[q * 2];
    float4 b1 = ((const float4*)bias)[q * 2 + 1];
    float2 s0 = __half22float2(*(const __half2*)&sr.x);
    float2 s1 = __half22float2(*(const __half2*)&sr.y);
    float2 s2 = __half22float2(*(const __half2*)&sr.z);
    float2 s3 = __half22float2(*(const __half2*)&sr.w);

    __half h[8];
    h[0] = __float2half(fmaxf(dc * a0 + dc2 * s0.x + b0.x, 0.f));
    h[1] = __float2half(fmaxf(dc * a1 + dc2 * s0.y + b0.y, 0.f));
    h[2] = __float2half(fmaxf(dc * a2 + dc2 * s1.x + b0.z, 0.f));
    h[3] = __float2half(fmaxf(dc * a3 + dc2 * s1.y + b0.w, 0.f));
    h[4] = __float2half(fmaxf(dc * a4 + dc2 * s2.x + b1.x, 0.f));
    h[5] = __float2half(fmaxf(dc * a5 + dc2 * s2.y + b1.y, 0.f));
    h[6] = __float2half(fmaxf(dc * a6 + dc2 * s3.x + b1.z, 0.f));
    h[7] = __float2half(fmaxf(dc * a7 + dc2 * s3.y + b1.w, 0.f));
    *(uint4*)(g_hcat + (size_t)c * HC + off + q * 8) = *(const uint4*)h;
}

// ---------------- launch ---------------------------------------------------
static inline int nb(int n, int b) { return (n + b - 1) / b; }
#define GEMM_SMEM (2 * STAGE_BYTES + 1024)

extern "C" void kernel_launch(void* const* d_in, const int* in_sizes, int n_in,
                              void* d_out, int out_size) {
    const float* x    = (const float*)d_in[0];
    const int*   ei   = (const int*)d_in[1];
    const int*   rowi = ei;          // edge_index[0] = source
    const int*   coli = ei + Ed;     // edge_index[1] = target
    const float* W[6];
    const float* b[6];
    for (int i = 0; i < 6; i++) {
        W[i] = (const float*)d_in[2 + 2 * i];
        b[i] = (const float*)d_in[3 + 2 * i];
    }
    const float* Wlin = (const float*)d_in[14];
    const float* blin = (const float*)d_in[15];
    float* out = (float*)d_out;

    cudaFuncSetAttribute(k_gemm_mma, cudaFuncAttributeMaxDynamicSharedMemorySize, GEMM_SMEM);

    k_zero_deg<<<nb(Nn, 256), 256>>>();
    k_count<<<nb(Ed, 256), 256>>>(coli);
    k_dinv<<<nb(Nn, 256), 256>>>();
    k_scan1<<<NB_SCAN, 256>>>();
    k_scan2<<<1, 512>>>();
    k_scan3<<<nb(Nn, 256), 256>>>();
    k_build<<<nb(Ed, 256), 256>>>(rowi, coli);
    k_convx<<<nb(Nn * 128, 256), 256>>>(x);
    k_convW_all<<<nb(315392, 256), 256>>>(W[0], W[1], W[2], W[3], W[4], W[5], Wlin);

    int gemm_grid = nb(Nn, 128);
    for (int i = 0; i < 6; i++) {
        int K   = Fdim + Hdim * i;        // 512,576,...,832
        int off = K;
        k_gemm_mma<<<gemm_grid, 256, GEMM_SMEM>>>(K, i, 0, nullptr, nullptr);
        k_agg_fused<<<nb(Nn * 8, 256), 256>>>(b[i], off);
    }

    k_gemm_mma<<<gemm_grid, 256, GEMM_SMEM>>>(HC, 6, 1, blin, out);
}

// round 17
// speedup vs baseline: 1.8892x; 1.0688x over previous
#include <cuda_runtime.h>
#include <cuda_fp16.h>
#include <cstdint>

#define Nn   100000
#define Fdim 512
#define Hdim 64
#define Cdim 40
#define Ed   1600000
#define HC   896      // F + 6*H  (hcat width)
#define NB_SCAN 391   // ceil(Nn/256)
#define WSLOT (64 * HC)

// ---------------- scratch (device globals; no allocation allowed) ----------
__device__ __half g_hcat[(size_t)Nn * HC];            // 179 MB, fp16
__device__ __half g_lin[(size_t)Nn * Hdim];           // GEMM output (64 cols, fp16)
__device__ float g_dinv[Nn];
__device__ int   g_deg[Nn];
__device__ int   g_off[Nn];                           // CSR offsets
__device__ int   g_cursor[Nn];
__device__ int   g_bsum[NB_SCAN];
__device__ int   g_esrc[Ed];                          // CSR: source node per edge slot
__device__ __half g_WtA[7 * WSLOT];                   // weights transposed [n][k], fp16

// ---------------- tiny PTX helpers ----------------------------------------
__device__ __forceinline__ uint32_t smem_u32(const void* p) {
    uint32_t a;
    asm("{ .reg .u64 t; cvta.to.shared.u64 t, %1; cvt.u32.u64 %0, t; }" : "=r"(a) : "l"(p));
    return a;
}
__device__ __forceinline__ uint32_t swz(uint32_t off) { return off ^ ((off >> 3) & 0x70); }

__device__ __forceinline__ void cp16(uint32_t dst, const void* src, int sz) {
    asm volatile("cp.async.cg.shared.global [%0], [%1], 16, %2;"
                 :: "r"(dst), "l"(src), "r"(sz) : "memory");
}
__device__ __forceinline__ void ldm_x4(uint32_t* r, uint32_t addr) {
    asm volatile("ldmatrix.sync.aligned.m8n8.x4.shared.b16 {%0,%1,%2,%3}, [%4];"
                 : "=r"(r[0]), "=r"(r[1]), "=r"(r[2]), "=r"(r[3]) : "r"(addr));
}
__device__ __forceinline__ void mma16816(float* d, const uint32_t* a, const uint32_t* b) {
    asm volatile("mma.sync.aligned.m16n8k16.row.col.f32.f16.f16.f32 "
                 "{%0,%1,%2,%3},{%4,%5,%6,%7},{%8,%9},{%0,%1,%2,%3};"
                 : "+f"(d[0]), "+f"(d[1]), "+f"(d[2]), "+f"(d[3])
                 : "r"(a[0]), "r"(a[1]), "r"(a[2]), "r"(a[3]), "r"(b[0]), "r"(b[1]));
}

// ---------------- degree / norm -------------------------------------------
__global__ void k_zero_deg() {
    int i = blockIdx.x * 256 + threadIdx.x;
    if (i < Nn) g_deg[i] = 0;
}
__global__ void k_count(const int* __restrict__ col) {
    int e = blockIdx.x * 256 + threadIdx.x;
    if (e < Ed) atomicAdd(&g_deg[col[e]], 1);
}
__global__ void k_dinv() {
    int i = blockIdx.x * 256 + threadIdx.x;
    if (i < Nn) g_dinv[i] = rsqrtf((float)(g_deg[i] + 1));  // +1 self loop
}

// ---------------- CSR build: scan + counting sort -------------------------
__global__ void k_scan1() {
    __shared__ int sh[256];
    int b = blockIdx.x, t = threadIdx.x;
    int i = b * 256 + t;
    int v = (i < Nn) ? g_deg[i] : 0;
    sh[t] = v;
    __syncthreads();
    int acc = v;
#pragma unroll
    for (int d = 1; d < 256; d <<= 1) {
        int u = (t >= d) ? sh[t - d] : 0;
        __syncthreads();
        acc += u;
        sh[t] = acc;
        __syncthreads();
    }
    if (i < Nn) g_off[i] = acc - v;
    if (t == 255) g_bsum[b] = acc;
}
__global__ void k_scan2() {
    __shared__ int sh[512];
    int t = threadIdx.x;
    int v = (t < NB_SCAN) ? g_bsum[t] : 0;
    sh[t] = v;
    __syncthreads();
    int acc = v;
#pragma unroll
    for (int d = 1; d < 512; d <<= 1) {
        int u = (t >= d) ? sh[t - d] : 0;
        __syncthreads();
        acc += u;
        sh[t] = acc;
        __syncthreads();
    }
    if (t < NB_SCAN) g_bsum[t] = acc - v;
}
__global__ void k_scan3() {
    int i = blockIdx.x * 256 + threadIdx.x;
    if (i >= Nn) return;
    int o = g_off[i] + g_bsum[i >> 8];
    g_off[i] = o;
    g_cursor[i] = o;
}
__global__ void k_build(const int* __restrict__ rowi, const int* __restrict__ coli) {
    int e = blockIdx.x * 256 + threadIdx.x;
    if (e >= Ed) return;
    int pos = atomicAdd(&g_cursor[coli[e]], 1);
    g_esrc[pos] = rowi[e];
}

// ---------------- convert x -> hcat fp16 [:, 0:512] -----------------------
__global__ void k_convx(const float* __restrict__ x) {
    int idx = blockIdx.x * 256 + threadIdx.x;     // Nn*128 float4s
    if (idx >= Nn * 128) return;
    int n = idx >> 7, q = idx & 127;
    float4 v = ((const float4*)x)[(size_t)n * 128 + q];
    __half h[4];
    h[0] = __float2half(v.x); h[1] = __float2half(v.y);
    h[2] = __float2half(v.z); h[3] = __float2half(v.w);
    *(uint2*)(g_hcat + (size_t)n * HC + q * 4) = *(const uint2*)h;
}

// ---------------- convert ALL weights upfront (fp16) ----------------------
__global__ void k_convW_all(const float* __restrict__ W0, const float* __restrict__ W1,
                            const float* __restrict__ W2, const float* __restrict__ W3,
                            const float* __restrict__ W4, const float* __restrict__ W5,
                            const float* __restrict__ Wlin) {
    const int base[8] = {0, 32768, 69632, 110592, 155648, 204800, 258048, 315392};
    const float* Ws[7] = {W0, W1, W2, W3, W4, W5, Wlin};
    int idx = blockIdx.x * 256 + threadIdx.x;
    if (idx >= 315392) return;
    int l = 0;
#pragma unroll
    for (int j = 1; j < 7; j++) if (idx >= base[j]) l = j;
    int e = idx - base[l];
    int k = e >> 6, n = e & 63;
    float w;
    if (l < 6) w = Ws[l][k * 64 + n];
    else       w = (n < Cdim) ? Ws[6][k * Cdim + n] : 0.f;
    g_WtA[(size_t)l * WSLOT + (size_t)n * HC + k] = __float2half(w);
}

// ---------------- mma.sync GEMM: g_lin[N,64] = hcat[:, :K] @ W ------------
// CTA: 256 rows x 64 cols, 256 threads / 8 warps (each warp 32x64, 2 m-tiles).
// A, B single fp16 (1 product). K-chunks of 64, double-buffered, SW128.
// Stage: A [0,32K) B [32K,40K).
// mode 0: write g_lin fp16.  mode 1: fused +blin, log_softmax, out[N,40] f32.
#define STAGE_BYTES 40960
__global__ void __launch_bounds__(256, 2) k_gemm_mma(int K, int wslot, int mode,
                                                     const float* __restrict__ blin,
                                                     float* __restrict__ out) {
    extern __shared__ char smem[];
    uint32_t sbase = smem_u32(smem);
    uint32_t data = (sbase + 1023) & ~1023u;

    int t = threadIdx.x, wid = t >> 5, lane = t & 31;
    int rowBase = blockIdx.x * 256;
    int m0 = wid * 32;
    const __half* Wt = g_WtA + (size_t)wslot * WSLOT;

    float acc[2][8][4];
#pragma unroll
    for (int mt = 0; mt < 2; mt++)
#pragma unroll
        for (int j = 0; j < 8; j++)
#pragma unroll
            for (int k = 0; k < 4; k++) acc[mt][j][k] = 0.f;

    auto load_chunk = [&](int c, int s) {
        uint32_t sa = data + s * STAGE_BYTES;
        // A: 256 rows x 64 k (128B/row) = 2048 cp16, 8 per thread
#pragma unroll
        for (int i = 0; i < 8; i++) {
            int idx = t + i * 256;           // 0..2047
            int r = idx >> 3, g = idx & 7;
            int gr = rowBase + r;
            int sz = (gr < Nn) ? 16 : 0;
            int grc = (gr < Nn) ? gr : (Nn - 1);
            size_t go = (size_t)grc * HC + c * 64 + g * 8;
            cp16(sa + swz(r * 128 + g * 16), g_hcat + go, sz);
        }
        // B: 64 n-rows x 64 k = 512 cp16, 2 per thread
#pragma unroll
        for (int i = 0; i < 2; i++) {
            int idx = t + i * 256;           // 0..511
            int n = idx >> 3, g = idx & 7;
            size_t go = (size_t)n * HC + c * 64 + g * 8;
            cp16(sa + 32768 + swz(n * 128 + g * 16), Wt + go, 16);
        }
        asm volatile("cp.async.commit_group;" ::: "memory");
    };

    int nC = K / 64;
    load_chunk(0, 0);
    load_chunk(1, 1);

    for (int c = 0; c < nC; c++) {
        int s = c & 1;
        if (c + 1 < nC) asm volatile("cp.async.wait_group 1;" ::: "memory");
        else            asm volatile("cp.async.wait_group 0;" ::: "memory");
        __syncthreads();

        uint32_t sa = data + s * STAGE_BYTES;
#pragma unroll
        for (int ks = 0; ks < 4; ks++) {
            // A fragments: 2 m-tiles (16x16 each)
            uint32_t a[2][4];
#pragma unroll
            for (int mt = 0; mt < 2; mt++) {
                int row = m0 + mt * 16 + (lane & 15);
                uint32_t off = swz(row * 128 + ks * 32 + (lane >> 4) * 16);
                ldm_x4(a[mt], sa + off);
            }
            // B fragments: x4 loads 2 n-tiles at once
            uint32_t bf[8][2];
#pragma unroll
            for (int j2 = 0; j2 < 4; j2++) {
                int nr = j2 * 16 + ((lane >> 4) * 8) + (lane & 7);
                int kh = (lane >> 3) & 1;
                uint32_t off = swz(nr * 128 + ks * 32 + kh * 16);
                uint32_t tmp[4];
                ldm_x4(tmp, sa + 32768 + off);
                bf[2 * j2][0] = tmp[0]; bf[2 * j2][1] = tmp[1];
                bf[2 * j2 + 1][0] = tmp[2]; bf[2 * j2 + 1][1] = tmp[3];
            }
#pragma unroll
            for (int mt = 0; mt < 2; mt++)
#pragma unroll
                for (int j = 0; j < 8; j++)
                    mma16816(acc[mt][j], a[mt], bf[j]);
        }
        __syncthreads();
        if (c + 2 < nC) load_chunk(c + 2, s);
    }

    int cBase = (lane & 3) * 2;

    if (mode == 0) {
#pragma unroll
        for (int mt = 0; mt < 2; mt++) {
            int rBase = rowBase + m0 + mt * 16 + (lane >> 2);
#pragma unroll
            for (int j = 0; j < 8; j++) {
                int col = j * 8 + cBase;
                if (rBase < Nn) {
                    __half2 h = __floats2half2_rn(acc[mt][j][0], acc[mt][j][1]);
                    *(uint32_t*)(g_lin + (size_t)rBase * 64 + col) = *(const uint32_t*)&h;
                }
                if (rBase + 8 < Nn) {
                    __half2 h = __floats2half2_rn(acc[mt][j][2], acc[mt][j][3]);
                    *(uint32_t*)(g_lin + (size_t)(rBase + 8) * 64 + col) = *(const uint32_t*)&h;
                }
            }
        }
    } else {
        // fused bias + log_softmax over valid cols 0..39 (j = 0..4 per thread).
#pragma unroll
        for (int mt = 0; mt < 2; mt++) {
            int rBase = rowBase + m0 + mt * 16 + (lane >> 2);
            float v0[10], v1[10];
            float mx0 = -3.0e38f, mx1 = -3.0e38f;
#pragma unroll
            for (int j = 0; j < 5; j++) {
                int col = j * 8 + cBase;
                float b0 = __ldg(&blin[col]), b1 = __ldg(&blin[col + 1]);
                v0[2 * j]     = acc[mt][j][0] + b0;
                v0[2 * j + 1] = acc[mt][j][1] + b1;
                v1[2 * j]     = acc[mt][j][2] + b0;
                v1[2 * j + 1] = acc[mt][j][3] + b1;
                mx0 = fmaxf(mx0, fmaxf(v0[2 * j], v0[2 * j + 1]));
                mx1 = fmaxf(mx1, fmaxf(v1[2 * j], v1[2 * j + 1]));
            }
            mx0 = fmaxf(mx0, __shfl_xor_sync(0xffffffffu, mx0, 1));
            mx0 = fmaxf(mx0, __shfl_xor_sync(0xffffffffu, mx0, 2));
            mx1 = fmaxf(mx1, __shfl_xor_sync(0xffffffffu, mx1, 1));
            mx1 = fmaxf(mx1, __shfl_xor_sync(0xffffffffu, mx1, 2));
            float s0 = 0.f, s1 = 0.f;
#pragma unroll
            for (int j = 0; j < 10; j++) {
                s0 += expf(v0[j] - mx0);
                s1 += expf(v1[j] - mx1);
            }
            s0 += __shfl_xor_sync(0xffffffffu, s0, 1);
            s0 += __shfl_xor_sync(0xffffffffu, s0, 2);
            s1 += __shfl_xor_sync(0xffffffffu, s1, 1);
            s1 += __shfl_xor_sync(0xffffffffu, s1, 2);
            float lg0 = mx0 + logf(s0), lg1 = mx1 + logf(s1);
#pragma unroll
            for (int j = 0; j < 5; j++) {
                int col = j * 8 + cBase;
                if (rBase < Nn)
                    *(float2*)(out + (size_t)rBase * Cdim + col) =
                        make_float2(v0[2 * j] - lg0, v0[2 * j + 1] - lg0);
                if (rBase + 8 < Nn)
                    *(float2*)(out + (size_t)(rBase + 8) * Cdim + col) =
                        make_float2(v1[2 * j] - lg1, v1[2 * j + 1] - lg1);
            }
        }
    }
}

// ---------------- fused CSR aggregate + self-loop + bias + relu -> fp16 ----
// 8 threads per node; thread q handles halves q*8..q*8+7 (16B uint4 loads).
// Edge loop unrolled x2 for MLP.
__global__ void k_agg_fused(const float* __restrict__ bias, int off) {
    int gid = blockIdx.x * 256 + threadIdx.x;
    int c = gid >> 3;
    if (c >= Nn) return;
    int q = gid & 7;

    int e0 = g_off[c];
    int d  = g_deg[c];
    float a0 = 0.f, a1 = 0.f, a2 = 0.f, a3 = 0.f;
    float a4 = 0.f, a5 = 0.f, a6 = 0.f, a7 = 0.f;

    int i = 0;
    for (; i + 2 <= d; i += 2) {
        int r0 = __ldg(&g_esrc[e0 + i]);
        int r1 = __ldg(&g_esrc[e0 + i + 1]);
        float w0 = __ldg(&g_dinv[r0]);
        float w1 = __ldg(&g_dinv[r1]);
        uint4 x0 = __ldg((const uint4*)(g_lin + (size_t)r0 * 64 + q * 8));
        uint4 x1 = __ldg((const uint4*)(g_lin + (size_t)r1 * 64 + q * 8));
        float2 p;
        p = __half22float2(*(const __half2*)&x0.x); a0 += w0 * p.x; a1 += w0 * p.y;
        p = __half22float2(*(const __half2*)&x0.y); a2 += w0 * p.x; a3 += w0 * p.y;
        p = __half22float2(*(const __half2*)&x0.z); a4 += w0 * p.x; a5 += w0 * p.y;
        p = __half22float2(*(const __half2*)&x0.w); a6 += w0 * p.x; a7 += w0 * p.y;
        p = __half22float2(*(const __half2*)&x1.x); a0 += w1 * p.x; a1 += w1 * p.y;
        p = __half22float2(*(const __half2*)&x1.y); a2 += w1 * p.x; a3 += w1 * p.y;
        p = __half22float2(*(const __half2*)&x1.z); a4 += w1 * p.x; a5 += w1 * p.y;
        p = __half22float2(*(const __half2*)&x1.w); a6 += w1 * p.x; a7 += w1 * p.y;
    }
    if (i < d) {
        int r0 = __ldg(&g_esrc[e0 + i]);
        float w0 = __ldg(&g_dinv[r0]);
        uint4 x0 = __ldg((const uint4*)(g_lin + (size_t)r0 * 64 + q * 8));
        float2 p;
        p = __half22float2(*(const __half2*)&x0.x); a0 += w0 * p.x; a1 += w0 * p.y;
        p = __half22float2(*(const __half2*)&x0.y); a2 += w0 * p.x; a3 += w0 * p.y;
        p = __half22float2(*(const __half2*)&x0.z); a4 += w0 * p.x; a5 += w0 * p.y;
        p = __half22float2(*(const __half2*)&x0.w); a6 += w0 * p.x; a7 += w0 * p.y;
    }

    float dc = g_dinv[c];
    float dc2 = dc * dc;
    uint4 sr = __ldg((const uint4*)(g_lin + (size_t)c * 64 + q * 8));
    float4 b0 = ((const float4*)bias)[q * 2];
    float4 b1 = ((const float4*)bias)[q * 2 + 1];
    float2 s0 = __half22float2(*(const __half2*)&sr.x);
    float2 s1 = __half22float2(*(const __half2*)&sr.y);
    float2 s2 = __half22float2(*(const __half2*)&sr.z);
    float2 s3 = __half22float2(*(const __half2*)&sr.w);

    __half h[8];
    h[0] = __float2half(fmaxf(dc * a0 + dc2 * s0.x + b0.x, 0.f));
    h[1] = __float2half(fmaxf(dc * a1 + dc2 * s0.y + b0.y, 0.f));
    h[2] = __float2half(fmaxf(dc * a2 + dc2 * s1.x + b0.z, 0.f));
    h[3] = __float2half(fmaxf(dc * a3 + dc2 * s1.y + b0.w, 0.f));
    h[4] = __float2half(fmaxf(dc * a4 + dc2 * s2.x + b1.x, 0.f));
    h[5] = __float2half(fmaxf(dc * a5 + dc2 * s2.y + b1.y, 0.f));
    h[6] = __float2half(fmaxf(dc * a6 + dc2 * s3.x + b1.z, 0.f));
    h[7] = __float2half(fmaxf(dc * a7 + dc2 * s3.y + b1.w, 0.f));
    *(uint4*)(g_hcat + (size_t)c * HC + off + q * 8) = *(const uint4*)h;
}

// ---------------- launch ---------------------------------------------------
static inline int nb(int n, int b) { return (n + b - 1) / b; }
#define GEMM_SMEM (2 * STAGE_BYTES + 1024)

extern "C" void kernel_launch(void* const* d_in, const int* in_sizes, int n_in,
                              void* d_out, int out_size) {
    const float* x    = (const float*)d_in[0];
    const int*   ei   = (const int*)d_in[1];
    const int*   rowi = ei;          // edge_index[0] = source
    const int*   coli = ei + Ed;     // edge_index[1] = target
    const float* W[6];
    const float* b[6];
    for (int i = 0; i < 6; i++) {
        W[i] = (const float*)d_in[2 + 2 * i];
        b[i] = (const float*)d_in[3 + 2 * i];
    }
    const float* Wlin = (const float*)d_in[14];
    const float* blin = (const float*)d_in[15];
    float* out = (float*)d_out;

    cudaFuncSetAttribute(k_gemm_mma, cudaFuncAttributeMaxDynamicSharedMemorySize, GEMM_SMEM);

    k_zero_deg<<<nb(Nn, 256), 256>>>();
    k_count<<<nb(Ed, 256), 256>>>(coli);
    k_dinv<<<nb(Nn, 256), 256>>>();
    k_scan1<<<NB_SCAN, 256>>>();
    k_scan2<<<1, 512>>>();
    k_scan3<<<nb(Nn, 256), 256>>>();
    k_build<<<nb(Ed, 256), 256>>>(rowi, coli);
    k_convx<<<nb(Nn * 128, 256), 256>>>(x);
    k_convW_all<<<nb(315392, 256), 256>>>(W[0], W[1], W[2], W[3], W[4], W[5], Wlin);

    int gemm_grid = nb(Nn, 256);
    for (int i = 0; i < 6; i++) {
        int K   = Fdim + Hdim * i;        // 512,576,...,832
        int off = K;
        k_gemm_mma<<<gemm_grid, 256, GEMM_SMEM>>>(K, i, 0, nullptr, nullptr);
        k_agg_fused<<<nb(Nn * 8, 256), 256>>>(b[i], off);
    }

    k_gemm_mma<<<gemm_grid, 256, GEMM_SMEM>>>(HC, 6, 1, blin, out);
}